// round 2
// baseline (speedup 1.0000x reference)
#include <cuda_runtime.h>
#include <math.h>

#define BB   8
#define NN   1024
#define FF   128
#define HH   8
#define MAXN 256
#define PRED_IN 384
#define LDIM 2
#define CH   16            // gather column-chunk (floats)

// ---------------- device scratch ----------------
__device__ int   g_nbr[BB * NN * MAXN];              // 8 MB
__device__ int   g_cnt[BB * NN];
__device__ float g_hp[BB * HH * NN * FF];            // 32 MB
__device__ float g_s[BB * HH * NN];
__device__ float g_d[BB * HH * NN];
__device__ float g_p[BB * HH * NN * MAXN];           // 64 MB normalized attn weights
__device__ float g_po[BB * HH * NN * FF];            // 32 MB per-head attn out
__device__ float g_x1[BB * NN * FF];
__device__ float g_x2[BB * NN * FF];
__device__ float g_x3[BB * NN * FF];
__device__ float g_pmax[BB * 8 * PRED_IN];

// ---------------- K1: adjacency -> neighbor lists (warp per row) -----------
__global__ __launch_bounds__(256) void build_nbr(const float* __restrict__ adj) {
    int wgl  = blockIdx.x * 8 + (threadIdx.x >> 5);
    int lane = threadIdx.x & 31;
    int b = wgl / NN;
    int i = wgl % NN;
    const float* row = adj + (size_t)(b * NN + i) * NN;
    int base = 0;
    for (int c = 0; c < NN; c += 32) {
        float v = row[c + lane];
        unsigned m = __ballot_sync(0xffffffffu, v > 0.0f);
        if (v > 0.0f) {
            int pos = base + __popc(m & ((1u << lane) - 1u));
            if (pos < MAXN) g_nbr[(b * NN + i) * MAXN + pos] = c + lane;
        }
        base += __popc(m);
    }
    if (lane == 0) g_cnt[b * NN + i] = min(base, MAXN);
}

// ---------------- K2: hp = x @ w[h] + fused tanh-dot epilogue --------------
// grid (64 m-tiles over 8192 rows, H). CTA 128x128, 256 thr, 8x8 microtile.
__global__ __launch_bounds__(256) void gat_gemm(const float* __restrict__ x,
                                                const float* __restrict__ w,
                                                const float* __restrict__ asrc,
                                                const float* __restrict__ adst) {
    const int mt = blockIdx.x;           // 0..63
    const int h  = blockIdx.y;
    const int b  = mt >> 3;
    const int n0 = (mt & 7) * 128;

    __shared__ float As[16][128];        // k-major
    __shared__ float Bs[16][128];
    __shared__ float sa[FF], da[FF];
    __shared__ float red[128][17];

    const int tid = threadIdx.x;
    const int tx = tid & 15;             // col group (8 cols)
    const int ty = tid >> 4;             // row group (8 rows)

    if (tid < FF) { sa[tid] = asrc[h * FF + tid]; da[tid] = adst[h * FF + tid]; }

    const float* xb = x + (size_t)(b * NN + n0) * FF;
    const float* wh = w + (size_t)h * FF * FF;

    float acc[8][8];
#pragma unroll
    for (int r = 0; r < 8; r++)
#pragma unroll
        for (int c = 0; c < 8; c++) acc[r][c] = 0.0f;

    const int arow = tid >> 2;           // 0..63
    const int akg  = tid & 3;            // 0..3 (4 k each)
    const int bk   = tid >> 5;           // 0..7
    const int bo   = (tid & 31) * 4;

    for (int k0 = 0; k0 < FF; k0 += 16) {
        // A: load x[row][k0+akg*4 ..+4], store transposed As[k][row]
#pragma unroll
        for (int i2 = 0; i2 < 2; i2++) {
            int row = arow + i2 * 64;
            float4 v = *(const float4*)&xb[(size_t)row * FF + k0 + akg * 4];
            As[akg * 4 + 0][row] = v.x;
            As[akg * 4 + 1][row] = v.y;
            As[akg * 4 + 2][row] = v.z;
            As[akg * 4 + 3][row] = v.w;
        }
        // B: direct copy
#pragma unroll
        for (int i2 = 0; i2 < 2; i2++)
            *(float4*)&Bs[bk + 8 * i2][bo] =
                *(const float4*)&wh[(size_t)(k0 + bk + 8 * i2) * FF + bo];
        __syncthreads();
#pragma unroll
        for (int kk = 0; kk < 16; kk++) {
            float4 a0 = *(const float4*)&As[kk][ty * 8];
            float4 a1 = *(const float4*)&As[kk][ty * 8 + 4];
            float4 b0 = *(const float4*)&Bs[kk][tx * 8];
            float4 b1 = *(const float4*)&Bs[kk][tx * 8 + 4];
            float av[8] = {a0.x, a0.y, a0.z, a0.w, a1.x, a1.y, a1.z, a1.w};
            float bv[8] = {b0.x, b0.y, b0.z, b0.w, b1.x, b1.y, b1.z, b1.w};
#pragma unroll
            for (int r = 0; r < 8; r++)
#pragma unroll
                for (int c = 0; c < 8; c++)
                    acc[r][c] = fmaf(av[r], bv[c], acc[r][c]);
        }
        __syncthreads();
    }

    // epilogue: write hp + per-row tanh-dot partials
    float* hpo = g_hp + (size_t)((b * HH + h) * NN + n0) * FF;
    float sp[8], dp[8];
#pragma unroll
    for (int r = 0; r < 8; r++) {
        int row = ty * 8 + r;
        *(float4*)&hpo[(size_t)row * FF + tx * 8] =
            make_float4(acc[r][0], acc[r][1], acc[r][2], acc[r][3]);
        *(float4*)&hpo[(size_t)row * FF + tx * 8 + 4] =
            make_float4(acc[r][4], acc[r][5], acc[r][6], acc[r][7]);
        float s = 0.0f, d = 0.0f;
#pragma unroll
        for (int c = 0; c < 8; c++) {
            float t = tanhf(acc[r][c]);
            s = fmaf(t, sa[tx * 8 + c], s);
            d = fmaf(t, da[tx * 8 + c], d);
        }
        sp[r] = s; dp[r] = d;
    }
#pragma unroll
    for (int r = 0; r < 8; r++) red[ty * 8 + r][tx] = sp[r];
    __syncthreads();
    if (tid < 128) {
        float s = 0.0f;
#pragma unroll
        for (int c = 0; c < 16; c++) s += red[tid][c];
        g_s[(b * HH + h) * NN + n0 + tid] = s;
    }
    __syncthreads();
#pragma unroll
    for (int r = 0; r < 8; r++) red[ty * 8 + r][tx] = dp[r];
    __syncthreads();
    if (tid < 128) {
        float d = 0.0f;
#pragma unroll
        for (int c = 0; c < 16; c++) d += red[tid][c];
        g_d[(b * HH + h) * NN + n0 + tid] = d;
    }
}

// ---------------- K3a: normalized attention weights ------------------------
// warp per (row, head). grid 8192 CTAs x 256 thr.
__global__ __launch_bounds__(256) void attn_weights() {
    const int wg   = blockIdx.x * 8 + (threadIdx.x >> 5);
    const int lane = threadIdx.x & 31;
    const int h  = wg & 7;
    const int ri = wg >> 3;          // 0..8191
    const int b  = ri >> 10;
    const int i  = ri & 1023;

    const int cnt = g_cnt[b * NN + i];
    const int* nb = &g_nbr[(b * NN + i) * MAXN];
    const float* dd = g_d + (b * HH + h) * NN;
    const float  si = g_s[(b * HH + h) * NN + i];
    float* pw = &g_p[(size_t)((b * HH + h) * NN + i) * MAXN];

    float m = -1e30f;
    float scv[8];
#pragma unroll
    for (int t = 0; t < 8; t++) {
        int k = lane + t * 32;
        float sc = -1e30f;
        if (k < cnt) {
            sc = si + dd[nb[k]];
            sc = sc >= 0.0f ? sc : 0.2f * sc;
        }
        scv[t] = sc;
        m = fmaxf(m, sc);
    }
#pragma unroll
    for (int off = 16; off > 0; off >>= 1)
        m = fmaxf(m, __shfl_xor_sync(0xffffffffu, m, off));

    float ssum = 0.0f;
    float ev[8];
#pragma unroll
    for (int t = 0; t < 8; t++) {
        int k = lane + t * 32;
        float e = 0.0f;
        if (k < cnt) e = __expf(scv[t] - m);
        ev[t] = e;
        ssum += e;
    }
#pragma unroll
    for (int off = 16; off > 0; off >>= 1)
        ssum += __shfl_xor_sync(0xffffffffu, ssum, off);
    const float wsc = (1.0f / (float)HH) / ssum;

#pragma unroll
    for (int t = 0; t < 8; t++) {
        int k = lane + t * 32;
        if (k < cnt) pw[k] = ev[t] * wsc;
    }
}

// ---------------- K3b: smem-staged sparse gather ---------------------------
// grid (8 chunks, H, B). CTA 256 thr, 64 KB dynamic smem (hp column slice).
__global__ __launch_bounds__(256) void gat_gather() {
    extern __shared__ float hp_s[];       // [1024][CH]
    const int chunk = blockIdx.x;
    const int h     = blockIdx.y;
    const int b     = blockIdx.z;
    const int c0    = chunk * CH;
    const int tid   = threadIdx.x;

    const float* hp = g_hp + (size_t)(b * HH + h) * NN * FF;

    // stage hp[:, c0:c0+16]
#pragma unroll
    for (int it = 0; it < 16; it++) {
        int idx = tid + it * 256;         // 0..4095
        int r  = idx >> 2;
        int cg = idx & 3;
        float4 v = *(const float4*)&hp[(size_t)r * FF + c0 + cg * 4];
        *(float4*)&hp_s[r * CH + cg * 4] = v;
    }
    __syncthreads();

    const int w     = tid >> 5;           // warp 0..7
    const int lane  = tid & 31;
    const int group = lane >> 2;          // 0..7 (edge within step)
    const int gl    = lane & 3;           // col quad

    for (int i = w; i < NN; i += 8) {
        const int cnt = g_cnt[b * NN + i];
        const int*   nb = &g_nbr[(b * NN + i) * MAXN];
        const float* pp = &g_p[(size_t)((b * HH + h) * NN + i) * MAXN];
        float ax = 0.0f, ay = 0.0f, az = 0.0f, aw = 0.0f;
        for (int k0 = 0; k0 < cnt; k0 += 8) {
            int ke = k0 + group;
            int   j = 0;
            float p = 0.0f;
            if (ke < cnt) { j = __ldg(nb + ke); p = __ldg(pp + ke); }
            float4 v = *(const float4*)&hp_s[j * CH + gl * 4];
            ax = fmaf(p, v.x, ax);
            ay = fmaf(p, v.y, ay);
            az = fmaf(p, v.z, az);
            aw = fmaf(p, v.w, aw);
        }
#pragma unroll
        for (int off = 16; off >= 4; off >>= 1) {
            ax += __shfl_xor_sync(0xffffffffu, ax, off);
            ay += __shfl_xor_sync(0xffffffffu, ay, off);
            az += __shfl_xor_sync(0xffffffffu, az, off);
            aw += __shfl_xor_sync(0xffffffffu, aw, off);
        }
        if (lane < 4)
            *(float4*)&g_po[(size_t)((b * HH + h) * NN + i) * FF + c0 + lane * 4] =
                make_float4(ax, ay, az, aw);
    }
}

// ---------------- K3c: reduce heads + bias (+ReLU) -------------------------
__global__ __launch_bounds__(256) void head_reduce(const float* __restrict__ bias,
                                                   float* __restrict__ xout,
                                                   int do_relu) {
    const int idx = blockIdx.x * 256 + threadIdx.x;   // float4 index, 262144 total
    const int ig  = idx >> 5;                          // global row 0..8191
    const int c4  = idx & 31;
    const int b   = ig >> 10;
    const int i   = ig & 1023;

    float ax = 0.0f, ay = 0.0f, az = 0.0f, aw = 0.0f;
#pragma unroll
    for (int h = 0; h < HH; h++) {
        float4 v = *(const float4*)&g_po[(size_t)((b * HH + h) * NN + i) * FF + c4 * 4];
        ax += v.x; ay += v.y; az += v.z; aw += v.w;
    }
    const float4 bv = *(const float4*)&bias[c4 * 4];
    ax += bv.x; ay += bv.y; az += bv.z; aw += bv.w;
    if (do_relu) {
        ax = fmaxf(ax, 0.0f); ay = fmaxf(ay, 0.0f);
        az = fmaxf(az, 0.0f); aw = fmaxf(aw, 0.0f);
    }
    *(float4*)&xout[(size_t)(b * NN + i) * FF + c4 * 4] = make_float4(ax, ay, az, aw);
}

// ---------------- K4/K5: concat max-pool + linear --------------------------
__global__ __launch_bounds__(PRED_IN) void pool1() {
    const int chunk = blockIdx.x;
    const int b     = blockIdx.y;
    const int f     = threadIdx.x;
    const float* src; int fo;
    if (f < 128)       { src = g_x1; fo = f; }
    else if (f < 256)  { src = g_x2; fo = f - 128; }
    else               { src = g_x3; fo = f - 256; }
    src += (size_t)b * NN * FF + fo;
    const int n0 = chunk * 128;
    float m = -INFINITY;
#pragma unroll 8
    for (int n = 0; n < 128; n++)
        m = fmaxf(m, src[(size_t)(n0 + n) * FF]);
    g_pmax[(b * 8 + chunk) * PRED_IN + f] = m;
}

__global__ __launch_bounds__(PRED_IN) void pool2(const float* __restrict__ pw,
                                                 const float* __restrict__ pb,
                                                 float* __restrict__ out) {
    __shared__ float pooled[PRED_IN];
    const int b = blockIdx.x;
    const int f = threadIdx.x;
    float m = -INFINITY;
#pragma unroll
    for (int c = 0; c < 8; c++)
        m = fmaxf(m, g_pmax[(b * 8 + c) * PRED_IN + f]);
    pooled[f] = m;
    __syncthreads();
    if (f < LDIM) {
        float acc = pb[f];
        for (int k = 0; k < PRED_IN; k++)
            acc = fmaf(pooled[k], pw[k * LDIM + f], acc);
        out[b * LDIM + f] = acc;
    }
}

// ---------------- launch ----------------------------------------------------
extern "C" void kernel_launch(void* const* d_in, const int* in_sizes, int n_in,
                              void* d_out, int out_size) {
    const float* x   = (const float*)d_in[0];
    const float* adj = (const float*)d_in[1];
    const float* w1  = (const float*)d_in[2];
    const float* as1 = (const float*)d_in[3];
    const float* ad1 = (const float*)d_in[4];
    const float* b1  = (const float*)d_in[5];
    const float* w2  = (const float*)d_in[6];
    const float* as2 = (const float*)d_in[7];
    const float* ad2 = (const float*)d_in[8];
    const float* b2  = (const float*)d_in[9];
    const float* w3  = (const float*)d_in[10];
    const float* as3 = (const float*)d_in[11];
    const float* ad3 = (const float*)d_in[12];
    const float* b3  = (const float*)d_in[13];
    const float* pw  = (const float*)d_in[14];
    const float* pb  = (const float*)d_in[15];
    float* out = (float*)d_out;

    float* x1; cudaGetSymbolAddress((void**)&x1, g_x1);
    float* x2; cudaGetSymbolAddress((void**)&x2, g_x2);
    float* x3; cudaGetSymbolAddress((void**)&x3, g_x3);

    static int smem_set = 0;
    if (!smem_set) {
        cudaFuncSetAttribute(gat_gather,
                             cudaFuncAttributeMaxDynamicSharedMemorySize,
                             NN * CH * sizeof(float));
        smem_set = 1;
    }
    const int gsm = NN * CH * sizeof(float);

    build_nbr<<<BB * NN / 8, 256>>>(adj);

    dim3 ggrid(64, HH);
    dim3 grgrid(FF / CH, HH, BB);
    const int wgrid = BB * NN * HH / 8;
    const int hrgrid = BB * NN * FF / 4 / 256;

    gat_gemm<<<ggrid, 256>>>(x,  w1, as1, ad1);
    attn_weights<<<wgrid, 256>>>();
    gat_gather<<<grgrid, 256, gsm>>>();
    head_reduce<<<hrgrid, 256>>>(b1, x1, 1);

    gat_gemm<<<ggrid, 256>>>(x1, w2, as2, ad2);
    attn_weights<<<wgrid, 256>>>();
    gat_gather<<<grgrid, 256, gsm>>>();
    head_reduce<<<hrgrid, 256>>>(b2, x2, 1);

    gat_gemm<<<ggrid, 256>>>(x2, w3, as3, ad3);
    attn_weights<<<wgrid, 256>>>();
    gat_gather<<<grgrid, 256, gsm>>>();
    head_reduce<<<hrgrid, 256>>>(b3, x3, 0);

    pool1<<<dim3(8, BB), PRED_IN>>>();
    pool2<<<BB, PRED_IN>>>(pw, pb, out);
}

// round 6
// speedup vs baseline: 1.5842x; 1.5842x over previous
#include <cuda_runtime.h>
#include <math.h>

#define BB   8
#define NN   1024
#define FF   128
#define HH   8
#define MAXN 256
#define PRED_IN 384
#define LDIM 2
#define CH   16            // gather column-chunk (floats)

// ---------------- device scratch ----------------
__device__ int   g_nbr[BB * NN * MAXN];              // 8 MB
__device__ int   g_cnt[BB * NN];
__device__ float g_hp[BB * HH * NN * FF];            // 32 MB
__device__ float g_s[BB * HH * NN];
__device__ float g_d[BB * HH * NN];
__device__ uint2 g_ep[(size_t)BB * HH * NN * MAXN];  // 128 MB packed {j, p}
__device__ float g_po[BB * HH * NN * FF];            // 32 MB per-head attn out
__device__ float g_x1[BB * NN * FF];
__device__ float g_x2[BB * NN * FF];
__device__ float g_x3[BB * NN * FF];
__device__ float g_pmax[BB * 8 * PRED_IN];

// ---------------- K1: adjacency -> neighbor lists (warp per row) -----------
__global__ __launch_bounds__(256) void build_nbr(const float* __restrict__ adj) {
    int wgl  = blockIdx.x * 8 + (threadIdx.x >> 5);
    int lane = threadIdx.x & 31;
    int b = wgl / NN;
    int i = wgl % NN;
    const float* row = adj + (size_t)(b * NN + i) * NN;
    int base = 0;
    for (int c = 0; c < NN; c += 32) {
        float v = row[c + lane];
        unsigned m = __ballot_sync(0xffffffffu, v > 0.0f);
        if (v > 0.0f) {
            int pos = base + __popc(m & ((1u << lane) - 1u));
            if (pos < MAXN) g_nbr[(b * NN + i) * MAXN + pos] = c + lane;
        }
        base += __popc(m);
    }
    if (lane == 0) g_cnt[b * NN + i] = min(base, MAXN);
}

// ---------------- K2: hp = x @ w[h] + fused tanh-dot epilogue --------------
// grid (64 m-tiles over 8192 rows, H). CTA 128x128, 256 thr, 8x8 microtile.
__global__ __launch_bounds__(256) void gat_gemm(const float* __restrict__ x,
                                                const float* __restrict__ w,
                                                const float* __restrict__ asrc,
                                                const float* __restrict__ adst) {
    const int mt = blockIdx.x;           // 0..63
    const int h  = blockIdx.y;
    const int b  = mt >> 3;
    const int n0 = (mt & 7) * 128;

    __shared__ float As[16][128];        // k-major
    __shared__ float Bs[16][128];
    __shared__ float sa[FF], da[FF];
    __shared__ float red[128][17];

    const int tid = threadIdx.x;
    const int tx = tid & 15;             // col group (8 cols)
    const int ty = tid >> 4;             // row group (8 rows)

    if (tid < FF) { sa[tid] = asrc[h * FF + tid]; da[tid] = adst[h * FF + tid]; }

    const float* xb = x + (size_t)(b * NN + n0) * FF;
    const float* wh = w + (size_t)h * FF * FF;

    float acc[8][8];
#pragma unroll
    for (int r = 0; r < 8; r++)
#pragma unroll
        for (int c = 0; c < 8; c++) acc[r][c] = 0.0f;

    const int arow = tid >> 2;           // 0..63
    const int akg  = tid & 3;            // 0..3 (4 k each)
    const int bk   = tid >> 5;           // 0..7
    const int bo   = (tid & 31) * 4;

    for (int k0 = 0; k0 < FF; k0 += 16) {
#pragma unroll
        for (int i2 = 0; i2 < 2; i2++) {
            int row = arow + i2 * 64;
            float4 v = *(const float4*)&xb[(size_t)row * FF + k0 + akg * 4];
            As[akg * 4 + 0][row] = v.x;
            As[akg * 4 + 1][row] = v.y;
            As[akg * 4 + 2][row] = v.z;
            As[akg * 4 + 3][row] = v.w;
        }
#pragma unroll
        for (int i2 = 0; i2 < 2; i2++)
            *(float4*)&Bs[bk + 8 * i2][bo] =
                *(const float4*)&wh[(size_t)(k0 + bk + 8 * i2) * FF + bo];
        __syncthreads();
#pragma unroll
        for (int kk = 0; kk < 16; kk++) {
            float4 a0 = *(const float4*)&As[kk][ty * 8];
            float4 a1 = *(const float4*)&As[kk][ty * 8 + 4];
            float4 b0 = *(const float4*)&Bs[kk][tx * 8];
            float4 b1 = *(const float4*)&Bs[kk][tx * 8 + 4];
            float av[8] = {a0.x, a0.y, a0.z, a0.w, a1.x, a1.y, a1.z, a1.w};
            float bv[8] = {b0.x, b0.y, b0.z, b0.w, b1.x, b1.y, b1.z, b1.w};
#pragma unroll
            for (int r = 0; r < 8; r++)
#pragma unroll
                for (int c = 0; c < 8; c++)
                    acc[r][c] = fmaf(av[r], bv[c], acc[r][c]);
        }
        __syncthreads();
    }

    float* hpo = g_hp + (size_t)((b * HH + h) * NN + n0) * FF;
    float sp[8], dp[8];
#pragma unroll
    for (int r = 0; r < 8; r++) {
        int row = ty * 8 + r;
        *(float4*)&hpo[(size_t)row * FF + tx * 8] =
            make_float4(acc[r][0], acc[r][1], acc[r][2], acc[r][3]);
        *(float4*)&hpo[(size_t)row * FF + tx * 8 + 4] =
            make_float4(acc[r][4], acc[r][5], acc[r][6], acc[r][7]);
        float s = 0.0f, d = 0.0f;
#pragma unroll
        for (int c = 0; c < 8; c++) {
            float t = tanhf(acc[r][c]);
            s = fmaf(t, sa[tx * 8 + c], s);
            d = fmaf(t, da[tx * 8 + c], d);
        }
        sp[r] = s; dp[r] = d;
    }
#pragma unroll
    for (int r = 0; r < 8; r++) red[ty * 8 + r][tx] = sp[r];
    __syncthreads();
    if (tid < 128) {
        float s = 0.0f;
#pragma unroll
        for (int c = 0; c < 16; c++) s += red[tid][c];
        g_s[(b * HH + h) * NN + n0 + tid] = s;
    }
    __syncthreads();
#pragma unroll
    for (int r = 0; r < 8; r++) red[ty * 8 + r][tx] = dp[r];
    __syncthreads();
    if (tid < 128) {
        float d = 0.0f;
#pragma unroll
        for (int c = 0; c < 16; c++) d += red[tid][c];
        g_d[(b * HH + h) * NN + n0 + tid] = d;
    }
}

// ---------------- K3a: normalized attention weights (packed {j,p}) ---------
// warp per (row, head). grid 8192 CTAs x 256 thr.
__global__ __launch_bounds__(256) void attn_weights() {
    const int wg   = blockIdx.x * 8 + (threadIdx.x >> 5);
    const int lane = threadIdx.x & 31;
    const int h  = wg & 7;
    const int ri = wg >> 3;
    const int b  = ri >> 10;
    const int i  = ri & 1023;

    const int cnt = g_cnt[b * NN + i];
    const int* nb = &g_nbr[(b * NN + i) * MAXN];
    const float* dd = g_d + (b * HH + h) * NN;
    const float  si = g_s[(b * HH + h) * NN + i];
    uint2* ep = &g_ep[(size_t)((b * HH + h) * NN + i) * MAXN];

    float m = -1e30f;
    float scv[8];
    int   jv[8];
#pragma unroll
    for (int t = 0; t < 8; t++) {
        int k = lane + t * 32;
        float sc = -1e30f;
        int j = 0;
        if (k < cnt) {
            j = nb[k];
            sc = si + dd[j];
            sc = sc >= 0.0f ? sc : 0.2f * sc;
        }
        jv[t] = j;
        scv[t] = sc;
        m = fmaxf(m, sc);
    }
#pragma unroll
    for (int off = 16; off > 0; off >>= 1)
        m = fmaxf(m, __shfl_xor_sync(0xffffffffu, m, off));

    float ssum = 0.0f;
    float ev[8];
#pragma unroll
    for (int t = 0; t < 8; t++) {
        int k = lane + t * 32;
        float e = 0.0f;
        if (k < cnt) e = __expf(scv[t] - m);
        ev[t] = e;
        ssum += e;
    }
#pragma unroll
    for (int off = 16; off > 0; off >>= 1)
        ssum += __shfl_xor_sync(0xffffffffu, ssum, off);
    const float wsc = (1.0f / (float)HH) / ssum;

#pragma unroll
    for (int t = 0; t < 8; t++) {
        int k = lane + t * 32;
        if (k < cnt)
            ep[k] = make_uint2((unsigned)jv[t], __float_as_uint(ev[t] * wsc));
    }
}

// ---------------- K3b: smem-staged gather, register-prefetched edges -------
// grid (8 chunks, H, B). 512 thr (16 warps). 64 KB dyn smem (hp column slice).
__global__ __launch_bounds__(512) void gat_gather() {
    extern __shared__ float hp_s[];       // [1024][CH]
    const int chunk = blockIdx.x;
    const int h     = blockIdx.y;
    const int b     = blockIdx.z;
    const int c0    = chunk * CH;
    const int tid   = threadIdx.x;

    const float* hp = g_hp + (size_t)(b * HH + h) * NN * FF;

    // stage hp[:, c0:c0+16]  (4096 float4, 512 threads x 8)
#pragma unroll
    for (int it = 0; it < 8; it++) {
        int idx = tid + it * 512;
        int r  = idx >> 2;
        int cg = idx & 3;
        *(float4*)&hp_s[r * CH + cg * 4] =
            *(const float4*)&hp[(size_t)r * FF + c0 + cg * 4];
    }
    __syncthreads();

    const int w     = tid >> 5;           // warp 0..15
    const int lane  = tid & 31;
    const int group = lane >> 2;          // 0..7  (edge slot within step)
    const int gl    = lane & 3;           // col quad

    for (int i = w; i < NN; i += 16) {
        const int cnt = g_cnt[b * NN + i];
        const uint2* ep = &g_ep[(size_t)((b * HH + h) * NN + i) * MAXN];
        float ax = 0.0f, ay = 0.0f, az = 0.0f, aw = 0.0f;

        for (int k0 = 0; k0 < cnt; k0 += 64) {
            // prefetch up to 8 edges for this lane's group (independent LDGs)
            uint2 r[8];
#pragma unroll
            for (int t = 0; t < 8; t++) {
                int e = k0 + t * 8 + group;
                r[t] = (e < cnt) ? __ldg(ep + e) : make_uint2(0u, 0u);
            }
#pragma unroll
            for (int t = 0; t < 8; t++) {
                int   j = (int)r[t].x;
                float p = __uint_as_float(r[t].y);
                float4 v = *(const float4*)&hp_s[j * CH + gl * 4];
                ax = fmaf(p, v.x, ax);
                ay = fmaf(p, v.y, ay);
                az = fmaf(p, v.z, az);
                aw = fmaf(p, v.w, aw);
            }
        }
#pragma unroll
        for (int off = 16; off >= 4; off >>= 1) {
            ax += __shfl_xor_sync(0xffffffffu, ax, off);
            ay += __shfl_xor_sync(0xffffffffu, ay, off);
            az += __shfl_xor_sync(0xffffffffu, az, off);
            aw += __shfl_xor_sync(0xffffffffu, aw, off);
        }
        if (lane < 4)
            *(float4*)&g_po[(size_t)((b * HH + h) * NN + i) * FF + c0 + lane * 4] =
                make_float4(ax, ay, az, aw);
    }
}

// ---------------- K3c: reduce heads + bias (+ReLU) -------------------------
__global__ __launch_bounds__(256) void head_reduce(const float* __restrict__ bias,
                                                   float* __restrict__ xout,
                                                   int do_relu) {
    const int idx = blockIdx.x * 256 + threadIdx.x;
    const int ig  = idx >> 5;
    const int c4  = idx & 31;
    const int b   = ig >> 10;
    const int i   = ig & 1023;

    float ax = 0.0f, ay = 0.0f, az = 0.0f, aw = 0.0f;
#pragma unroll
    for (int h = 0; h < HH; h++) {
        float4 v = *(const float4*)&g_po[(size_t)((b * HH + h) * NN + i) * FF + c4 * 4];
        ax += v.x; ay += v.y; az += v.z; aw += v.w;
    }
    const float4 bv = *(const float4*)&bias[c4 * 4];
    ax += bv.x; ay += bv.y; az += bv.z; aw += bv.w;
    if (do_relu) {
        ax = fmaxf(ax, 0.0f); ay = fmaxf(ay, 0.0f);
        az = fmaxf(az, 0.0f); aw = fmaxf(aw, 0.0f);
    }
    *(float4*)&xout[(size_t)(b * NN + i) * FF + c4 * 4] = make_float4(ax, ay, az, aw);
}

// ---------------- K4/K5: concat max-pool + linear --------------------------
__global__ __launch_bounds__(PRED_IN) void pool1() {
    const int chunk = blockIdx.x;
    const int b     = blockIdx.y;
    const int f     = threadIdx.x;
    const float* src; int fo;
    if (f < 128)       { src = g_x1; fo = f; }
    else if (f < 256)  { src = g_x2; fo = f - 128; }
    else               { src = g_x3; fo = f - 256; }
    src += (size_t)b * NN * FF + fo;
    const int n0 = chunk * 128;
    float m = -INFINITY;
#pragma unroll 8
    for (int n = 0; n < 128; n++)
        m = fmaxf(m, src[(size_t)(n0 + n) * FF]);
    g_pmax[(b * 8 + chunk) * PRED_IN + f] = m;
}

__global__ __launch_bounds__(PRED_IN) void pool2(const float* __restrict__ pw,
                                                 const float* __restrict__ pb,
                                                 float* __restrict__ out) {
    __shared__ float pooled[PRED_IN];
    const int b = blockIdx.x;
    const int f = threadIdx.x;
    float m = -INFINITY;
#pragma unroll
    for (int c = 0; c < 8; c++)
        m = fmaxf(m, g_pmax[(b * 8 + c) * PRED_IN + f]);
    pooled[f] = m;
    __syncthreads();
    if (f < LDIM) {
        float acc = pb[f];
        for (int k = 0; k < PRED_IN; k++)
            acc = fmaf(pooled[k], pw[k * LDIM + f], acc);
        out[b * LDIM + f] = acc;
    }
}

// ---------------- launch ----------------------------------------------------
extern "C" void kernel_launch(void* const* d_in, const int* in_sizes, int n_in,
                              void* d_out, int out_size) {
    const float* x   = (const float*)d_in[0];
    const float* adj = (const float*)d_in[1];
    const float* w1  = (const float*)d_in[2];
    const float* as1 = (const float*)d_in[3];
    const float* ad1 = (const float*)d_in[4];
    const float* b1  = (const float*)d_in[5];
    const float* w2  = (const float*)d_in[6];
    const float* as2 = (const float*)d_in[7];
    const float* ad2 = (const float*)d_in[8];
    const float* b2  = (const float*)d_in[9];
    const float* w3  = (const float*)d_in[10];
    const float* as3 = (const float*)d_in[11];
    const float* ad3 = (const float*)d_in[12];
    const float* b3  = (const float*)d_in[13];
    const float* pw  = (const float*)d_in[14];
    const float* pb  = (const float*)d_in[15];
    float* out = (float*)d_out;

    float* x1; cudaGetSymbolAddress((void**)&x1, g_x1);
    float* x2; cudaGetSymbolAddress((void**)&x2, g_x2);
    float* x3; cudaGetSymbolAddress((void**)&x3, g_x3);

    static int smem_set = 0;
    if (!smem_set) {
        cudaFuncSetAttribute(gat_gather,
                             cudaFuncAttributeMaxDynamicSharedMemorySize,
                             NN * CH * sizeof(float));
        smem_set = 1;
    }
    const int gsm = NN * CH * sizeof(float);

    build_nbr<<<BB * NN / 8, 256>>>(adj);

    dim3 ggrid(64, HH);
    dim3 grgrid(FF / CH, HH, BB);
    const int wgrid = BB * NN * HH / 8;
    const int hrgrid = BB * NN * FF / 4 / 256;

    gat_gemm<<<ggrid, 256>>>(x,  w1, as1, ad1);
    attn_weights<<<wgrid, 256>>>();
    gat_gather<<<grgrid, 512, gsm>>>();
    head_reduce<<<hrgrid, 256>>>(b1, x1, 1);

    gat_gemm<<<ggrid, 256>>>(x1, w2, as2, ad2);
    attn_weights<<<wgrid, 256>>>();
    gat_gather<<<grgrid, 512, gsm>>>();
    head_reduce<<<hrgrid, 256>>>(b2, x2, 1);

    gat_gemm<<<ggrid, 256>>>(x2, w3, as3, ad3);
    attn_weights<<<wgrid, 256>>>();
    gat_gather<<<grgrid, 512, gsm>>>();
    head_reduce<<<hrgrid, 256>>>(b3, x3, 0);

    pool1<<<dim3(8, BB), PRED_IN>>>();
    pool2<<<BB, PRED_IN>>>(pw, pb, out);
}

// round 8
// speedup vs baseline: 1.7928x; 1.1317x over previous
#include <cuda_runtime.h>
#include <math.h>

#define BB   8
#define NN   1024
#define FF   128
#define HH   8
#define MAXN 256
#define PRED_IN 384
#define LDIM 2

// ---------------- device scratch ----------------
__device__ int   g_nbr[BB * NN * MAXN];              // 8 MB
__device__ int   g_cnt[BB * NN];
__device__ int   g_qoff[BB * NN * 4];                // per-row j-quartile cumulative offsets
__device__ float g_hp[BB * HH * NN * FF];            // 32 MB
__device__ float g_s[BB * HH * NN];
__device__ float g_d[BB * HH * NN];
__device__ uint2 g_ep[(size_t)BB * HH * NN * MAXN];  // packed {j, p(fp32)}
__device__ float g_po[BB * HH * NN * FF];            // 32 MB per-head attn out
__device__ float g_x1[BB * NN * FF];
__device__ float g_x2[BB * NN * FF];
__device__ float g_x3[BB * NN * FF];
__device__ float g_pmax[BB * 8 * PRED_IN];

// ---------------- K1: adjacency -> neighbor lists + quartile offsets -------
__global__ __launch_bounds__(256) void build_nbr(const float* __restrict__ adj) {
    int wgl  = blockIdx.x * 8 + (threadIdx.x >> 5);
    int lane = threadIdx.x & 31;
    int b = wgl / NN;
    int i = wgl % NN;
    const float* row = adj + (size_t)(b * NN + i) * NN;
    int base = 0;
    int qof[4];
    for (int c = 0; c < NN; c += 32) {
        float v = row[c + lane];
        unsigned m = __ballot_sync(0xffffffffu, v > 0.0f);
        if (v > 0.0f) {
            int pos = base + __popc(m & ((1u << lane) - 1u));
            if (pos < MAXN) g_nbr[(b * NN + i) * MAXN + pos] = c + lane;
        }
        base += __popc(m);
        if (((c + 32) & 255) == 0)
            qof[((c + 32) >> 8) - 1] = min(base, MAXN);
    }
    if (lane == 0) {
        g_cnt[b * NN + i] = min(base, MAXN);
        *(int4*)&g_qoff[(b * NN + i) * 4] =
            make_int4(qof[0], qof[1], qof[2], qof[3]);
    }
}

// ---------------- K2: hp = x @ w[h] + fused tanh-dot epilogue --------------
__global__ __launch_bounds__(256) void gat_gemm(const float* __restrict__ x,
                                                const float* __restrict__ w,
                                                const float* __restrict__ asrc,
                                                const float* __restrict__ adst) {
    const int mt = blockIdx.x;           // 0..63
    const int h  = blockIdx.y;
    const int b  = mt >> 3;
    const int n0 = (mt & 7) * 128;

    __shared__ float As[16][128];        // k-major
    __shared__ float Bs[16][128];
    __shared__ float sa[FF], da[FF];
    __shared__ float red[128][17];

    const int tid = threadIdx.x;
    const int tx = tid & 15;
    const int ty = tid >> 4;

    if (tid < FF) { sa[tid] = asrc[h * FF + tid]; da[tid] = adst[h * FF + tid]; }

    const float* xb = x + (size_t)(b * NN + n0) * FF;
    const float* wh = w + (size_t)h * FF * FF;

    float acc[8][8];
#pragma unroll
    for (int r = 0; r < 8; r++)
#pragma unroll
        for (int c = 0; c < 8; c++) acc[r][c] = 0.0f;

    const int arow = tid >> 2;
    const int akg  = tid & 3;
    const int bk   = tid >> 5;
    const int bo   = (tid & 31) * 4;

    for (int k0 = 0; k0 < FF; k0 += 16) {
#pragma unroll
        for (int i2 = 0; i2 < 2; i2++) {
            int row = arow + i2 * 64;
            float4 v = *(const float4*)&xb[(size_t)row * FF + k0 + akg * 4];
            As[akg * 4 + 0][row] = v.x;
            As[akg * 4 + 1][row] = v.y;
            As[akg * 4 + 2][row] = v.z;
            As[akg * 4 + 3][row] = v.w;
        }
#pragma unroll
        for (int i2 = 0; i2 < 2; i2++)
            *(float4*)&Bs[bk + 8 * i2][bo] =
                *(const float4*)&wh[(size_t)(k0 + bk + 8 * i2) * FF + bo];
        __syncthreads();
#pragma unroll
        for (int kk = 0; kk < 16; kk++) {
            float4 a0 = *(const float4*)&As[kk][ty * 8];
            float4 a1 = *(const float4*)&As[kk][ty * 8 + 4];
            float4 b0 = *(const float4*)&Bs[kk][tx * 8];
            float4 b1 = *(const float4*)&Bs[kk][tx * 8 + 4];
            float av[8] = {a0.x, a0.y, a0.z, a0.w, a1.x, a1.y, a1.z, a1.w};
            float bv[8] = {b0.x, b0.y, b0.z, b0.w, b1.x, b1.y, b1.z, b1.w};
#pragma unroll
            for (int r = 0; r < 8; r++)
#pragma unroll
                for (int c = 0; c < 8; c++)
                    acc[r][c] = fmaf(av[r], bv[c], acc[r][c]);
        }
        __syncthreads();
    }

    float* hpo = g_hp + (size_t)((b * HH + h) * NN + n0) * FF;
    float sp[8], dp[8];
#pragma unroll
    for (int r = 0; r < 8; r++) {
        int row = ty * 8 + r;
        *(float4*)&hpo[(size_t)row * FF + tx * 8] =
            make_float4(acc[r][0], acc[r][1], acc[r][2], acc[r][3]);
        *(float4*)&hpo[(size_t)row * FF + tx * 8 + 4] =
            make_float4(acc[r][4], acc[r][5], acc[r][6], acc[r][7]);
        float s = 0.0f, d = 0.0f;
#pragma unroll
        for (int c = 0; c < 8; c++) {
            float t = tanhf(acc[r][c]);
            s = fmaf(t, sa[tx * 8 + c], s);
            d = fmaf(t, da[tx * 8 + c], d);
        }
        sp[r] = s; dp[r] = d;
    }
#pragma unroll
    for (int r = 0; r < 8; r++) red[ty * 8 + r][tx] = sp[r];
    __syncthreads();
    if (tid < 128) {
        float s = 0.0f;
#pragma unroll
        for (int c = 0; c < 16; c++) s += red[tid][c];
        g_s[(b * HH + h) * NN + n0 + tid] = s;
    }
    __syncthreads();
#pragma unroll
    for (int r = 0; r < 8; r++) red[ty * 8 + r][tx] = dp[r];
    __syncthreads();
    if (tid < 128) {
        float d = 0.0f;
#pragma unroll
        for (int c = 0; c < 16; c++) d += red[tid][c];
        g_d[(b * HH + h) * NN + n0 + tid] = d;
    }
}

// ---------------- K3a: normalized attention weights (packed {j,p}) ---------
__global__ __launch_bounds__(256) void attn_weights() {
    const int wg   = blockIdx.x * 8 + (threadIdx.x >> 5);
    const int lane = threadIdx.x & 31;
    const int h  = wg & 7;
    const int ri = wg >> 3;
    const int b  = ri >> 10;
    const int i  = ri & 1023;

    const int cnt = g_cnt[b * NN + i];
    const int* nb = &g_nbr[(b * NN + i) * MAXN];
    const float* dd = g_d + (b * HH + h) * NN;
    const float  si = g_s[(b * HH + h) * NN + i];
    uint2* ep = &g_ep[(size_t)((b * HH + h) * NN + i) * MAXN];

    float m = -1e30f;
    float scv[8];
    int   jv[8];
#pragma unroll
    for (int t = 0; t < 8; t++) {
        int k = lane + t * 32;
        float sc = -1e30f;
        int j = 0;
        if (k < cnt) {
            j = nb[k];
            sc = si + dd[j];
            sc = sc >= 0.0f ? sc : 0.2f * sc;
        }
        jv[t] = j;
        scv[t] = sc;
        m = fmaxf(m, sc);
    }
#pragma unroll
    for (int off = 16; off > 0; off >>= 1)
        m = fmaxf(m, __shfl_xor_sync(0xffffffffu, m, off));

    float ssum = 0.0f;
    float ev[8];
#pragma unroll
    for (int t = 0; t < 8; t++) {
        int k = lane + t * 32;
        float e = 0.0f;
        if (k < cnt) e = __expf(scv[t] - m);
        ev[t] = e;
        ssum += e;
    }
#pragma unroll
    for (int off = 16; off > 0; off >>= 1)
        ssum += __shfl_xor_sync(0xffffffffu, ssum, off);
    const float wsc = (1.0f / (float)HH) / ssum;

#pragma unroll
    for (int t = 0; t < 8; t++) {
        int k = lane + t * 32;
        if (k < cnt)
            ep[k] = make_uint2((unsigned)jv[t], __float_as_uint(ev[t] * wsc));
    }
}

// ---------------- K3b: full-row smem gather, 4 j-quarter passes ------------
// grid (2 rowsplit, H, B) = 128 CTAs, 1024 thr, 128 KB dyn smem.
// Warp owns row i; lane owns its float4 of the 128-wide output.
__global__ __launch_bounds__(1024) void gat_gather() {
    extern __shared__ float hp_s[];       // [256][128]
    const int rs  = blockIdx.x;           // 0..1
    const int h   = blockIdx.y;
    const int b   = blockIdx.z;
    const int tid = threadIdx.x;
    const int w   = tid >> 5;             // 0..31
    const int lane = tid & 31;
    const int bh  = b * HH + h;

    const float* hp = g_hp + (size_t)bh * NN * FF;
    float*       po = g_po + (size_t)bh * NN * FF;

    for (int pass = 0; pass < 4; pass++) {
        __syncthreads();                  // previous pass done reading hp_s
        const float* src = hp + (size_t)pass * 256 * FF;
#pragma unroll
        for (int it = 0; it < 8; it++) {
            int idx = tid + it * 1024;    // 8192 float4 = 128 KB
            *(float4*)&hp_s[idx * 4] = *(const float4*)&src[idx * 4];
        }
        __syncthreads();

#pragma unroll 1
        for (int ii = 0; ii < 16; ii++) {
            const int i = rs * 512 + ii * 32 + w;
            const int4 q = *(const int4*)&g_qoff[(b * NN + i) * 4];
            const int lo = (pass == 0) ? 0 :
                           (pass == 1) ? q.x : (pass == 2) ? q.y : q.z;
            const int hi = (pass == 0) ? q.x :
                           (pass == 1) ? q.y : (pass == 2) ? q.z : q.w;
            const uint2* ep = &g_ep[(size_t)(bh * NN + i) * MAXN];

            float ax = 0.0f, ay = 0.0f, az = 0.0f, aw2 = 0.0f;
            for (int k0 = lo; k0 < hi; k0 += 8) {
                uint2 r[8];
#pragma unroll
                for (int t = 0; t < 8; t++)
                    r[t] = (k0 + t < hi) ? __ldg(ep + k0 + t)
                                         : make_uint2(0u, 0u);
#pragma unroll
                for (int t = 0; t < 8; t++) {
                    const int   j = (int)(r[t].x & 255u);
                    const float p = __uint_as_float(r[t].y);
                    float4 v = *(const float4*)&hp_s[j * FF + lane * 4];
                    ax = fmaf(p, v.x, ax);
                    ay = fmaf(p, v.y, ay);
                    az = fmaf(p, v.z, az);
                    aw2 = fmaf(p, v.w, aw2);
                }
            }
            float* dst = &po[(size_t)i * FF + lane * 4];
            if (pass == 0) {
                *(float4*)dst = make_float4(ax, ay, az, aw2);
            } else {
                float4 o = *(const float4*)dst;
                *(float4*)dst = make_float4(o.x + ax, o.y + ay,
                                            o.z + az, o.w + aw2);
            }
        }
    }
}

// ---------------- K3c: reduce heads + bias (+ReLU) -------------------------
__global__ __launch_bounds__(256) void head_reduce(const float* __restrict__ bias,
                                                   float* __restrict__ xout,
                                                   int do_relu) {
    const int idx = blockIdx.x * 256 + threadIdx.x;
    const int ig  = idx >> 5;
    const int c4  = idx & 31;
    const int b   = ig >> 10;
    const int i   = ig & 1023;

    float ax = 0.0f, ay = 0.0f, az = 0.0f, aw = 0.0f;
#pragma unroll
    for (int h = 0; h < HH; h++) {
        float4 v = *(const float4*)&g_po[(size_t)((b * HH + h) * NN + i) * FF + c4 * 4];
        ax += v.x; ay += v.y; az += v.z; aw += v.w;
    }
    const float4 bv = *(const float4*)&bias[c4 * 4];
    ax += bv.x; ay += bv.y; az += bv.z; aw += bv.w;
    if (do_relu) {
        ax = fmaxf(ax, 0.0f); ay = fmaxf(ay, 0.0f);
        az = fmaxf(az, 0.0f); aw = fmaxf(aw, 0.0f);
    }
    *(float4*)&xout[(size_t)(b * NN + i) * FF + c4 * 4] = make_float4(ax, ay, az, aw);
}

// ---------------- K4/K5: concat max-pool + linear --------------------------
__global__ __launch_bounds__(PRED_IN) void pool1() {
    const int chunk = blockIdx.x;
    const int b     = blockIdx.y;
    const int f     = threadIdx.x;
    const float* src; int fo;
    if (f < 128)       { src = g_x1; fo = f; }
    else if (f < 256)  { src = g_x2; fo = f - 128; }
    else               { src = g_x3; fo = f - 256; }
    src += (size_t)b * NN * FF + fo;
    const int n0 = chunk * 128;
    float m = -INFINITY;
#pragma unroll 8
    for (int n = 0; n < 128; n++)
        m = fmaxf(m, src[(size_t)(n0 + n) * FF]);
    g_pmax[(b * 8 + chunk) * PRED_IN + f] = m;
}

__global__ __launch_bounds__(PRED_IN) void pool2(const float* __restrict__ pw,
                                                 const float* __restrict__ pb,
                                                 float* __restrict__ out) {
    __shared__ float pooled[PRED_IN];
    const int b = blockIdx.x;
    const int f = threadIdx.x;
    float m = -INFINITY;
#pragma unroll
    for (int c = 0; c < 8; c++)
        m = fmaxf(m, g_pmax[(b * 8 + c) * PRED_IN + f]);
    pooled[f] = m;
    __syncthreads();
    if (f < LDIM) {
        float acc = pb[f];
        for (int k = 0; k < PRED_IN; k++)
            acc = fmaf(pooled[k], pw[k * LDIM + f], acc);
        out[b * LDIM + f] = acc;
    }
}

// ---------------- launch ----------------------------------------------------
extern "C" void kernel_launch(void* const* d_in, const int* in_sizes, int n_in,
                              void* d_out, int out_size) {
    const float* x   = (const float*)d_in[0];
    const float* adj = (const float*)d_in[1];
    const float* w1  = (const float*)d_in[2];
    const float* as1 = (const float*)d_in[3];
    const float* ad1 = (const float*)d_in[4];
    const float* b1  = (const float*)d_in[5];
    const float* w2  = (const float*)d_in[6];
    const float* as2 = (const float*)d_in[7];
    const float* ad2 = (const float*)d_in[8];
    const float* b2  = (const float*)d_in[9];
    const float* w3  = (const float*)d_in[10];
    const float* as3 = (const float*)d_in[11];
    const float* ad3 = (const float*)d_in[12];
    const float* b3  = (const float*)d_in[13];
    const float* pw  = (const float*)d_in[14];
    const float* pb  = (const float*)d_in[15];
    float* out = (float*)d_out;

    float* x1; cudaGetSymbolAddress((void**)&x1, g_x1);
    float* x2; cudaGetSymbolAddress((void**)&x2, g_x2);
    float* x3; cudaGetSymbolAddress((void**)&x3, g_x3);

    const int gsm = 256 * FF * sizeof(float);     // 128 KB
    static int smem_set = 0;
    if (!smem_set) {
        cudaFuncSetAttribute(gat_gather,
                             cudaFuncAttributeMaxDynamicSharedMemorySize, gsm);
        smem_set = 1;
    }

    build_nbr<<<BB * NN / 8, 256>>>(adj);

    dim3 ggrid(64, HH);
    dim3 grgrid(2, HH, BB);
    const int wgrid = BB * NN * HH / 8;
    const int hrgrid = BB * NN * FF / 4 / 256;

    gat_gemm<<<ggrid, 256>>>(x,  w1, as1, ad1);
    attn_weights<<<wgrid, 256>>>();
    gat_gather<<<grgrid, 1024, gsm>>>();
    head_reduce<<<hrgrid, 256>>>(b1, x1, 1);

    gat_gemm<<<ggrid, 256>>>(x1, w2, as2, ad2);
    attn_weights<<<wgrid, 256>>>();
    gat_gather<<<grgrid, 1024, gsm>>>();
    head_reduce<<<hrgrid, 256>>>(b2, x2, 1);

    gat_gemm<<<ggrid, 256>>>(x2, w3, as3, ad3);
    attn_weights<<<wgrid, 256>>>();
    gat_gather<<<grgrid, 1024, gsm>>>();
    head_reduce<<<hrgrid, 256>>>(b3, x3, 0);

    pool1<<<dim3(8, BB), PRED_IN>>>();
    pool2<<<BB, PRED_IN>>>(pw, pb, out);
}

// round 9
// speedup vs baseline: 1.7978x; 1.0028x over previous
#include <cuda_runtime.h>
#include <math.h>

#define BB   8
#define NN   1024
#define FF   128
#define HH   8
#define MAXN 256
#define PRED_IN 384
#define LDIM 2

// ---------------- device scratch ----------------
__device__ int   g_nbr[BB * NN * MAXN];              // 8 MB
__device__ int   g_cnt[BB * NN];
__device__ int   g_qoff[BB * NN * 4];                // per-row j-quartile cumulative offsets
__device__ float g_hp[BB * HH * NN * FF];            // 32 MB
__device__ float g_s[BB * HH * NN];
__device__ float g_d[BB * HH * NN];
__device__ uint2 g_ep[(size_t)BB * HH * NN * MAXN];  // packed {local byte off, p}
__device__ float g_po4[(size_t)4 * BB * HH * NN * FF]; // 134 MB quarter partials
__device__ float g_x1[BB * NN * FF];
__device__ float g_x2[BB * NN * FF];
__device__ float g_x3[BB * NN * FF];
__device__ float g_pmax[BB * 8 * PRED_IN];

// ---------------- K1: adjacency -> neighbor lists + quartile offsets -------
__global__ __launch_bounds__(256) void build_nbr(const float* __restrict__ adj) {
    int wgl  = blockIdx.x * 8 + (threadIdx.x >> 5);
    int lane = threadIdx.x & 31;
    int b = wgl / NN;
    int i = wgl % NN;
    const float* row = adj + (size_t)(b * NN + i) * NN;
    int base = 0;
    int qof[4];
    for (int c = 0; c < NN; c += 32) {
        float v = row[c + lane];
        unsigned m = __ballot_sync(0xffffffffu, v > 0.0f);
        if (v > 0.0f) {
            int pos = base + __popc(m & ((1u << lane) - 1u));
            if (pos < MAXN) g_nbr[(b * NN + i) * MAXN + pos] = c + lane;
        }
        base += __popc(m);
        if (((c + 32) & 255) == 0)
            qof[((c + 32) >> 8) - 1] = min(base, MAXN);
    }
    if (lane == 0) {
        g_cnt[b * NN + i] = min(base, MAXN);
        *(int4*)&g_qoff[(b * NN + i) * 4] =
            make_int4(qof[0], qof[1], qof[2], qof[3]);
    }
}

// ---------------- K2: hp = x @ w[h] + fused tanh-dot epilogue --------------
__global__ __launch_bounds__(256) void gat_gemm(const float* __restrict__ x,
                                                const float* __restrict__ w,
                                                const float* __restrict__ asrc,
                                                const float* __restrict__ adst) {
    const int mt = blockIdx.x;           // 0..63
    const int h  = blockIdx.y;
    const int b  = mt >> 3;
    const int n0 = (mt & 7) * 128;

    __shared__ float As[16][128];        // k-major
    __shared__ float Bs[16][128];
    __shared__ float sa[FF], da[FF];
    __shared__ float red[128][17];

    const int tid = threadIdx.x;
    const int tx = tid & 15;
    const int ty = tid >> 4;

    if (tid < FF) { sa[tid] = asrc[h * FF + tid]; da[tid] = adst[h * FF + tid]; }

    const float* xb = x + (size_t)(b * NN + n0) * FF;
    const float* wh = w + (size_t)h * FF * FF;

    float acc[8][8];
#pragma unroll
    for (int r = 0; r < 8; r++)
#pragma unroll
        for (int c = 0; c < 8; c++) acc[r][c] = 0.0f;

    const int arow = tid >> 2;
    const int akg  = tid & 3;
    const int bk   = tid >> 5;
    const int bo   = (tid & 31) * 4;

    for (int k0 = 0; k0 < FF; k0 += 16) {
#pragma unroll
        for (int i2 = 0; i2 < 2; i2++) {
            int row = arow + i2 * 64;
            float4 v = *(const float4*)&xb[(size_t)row * FF + k0 + akg * 4];
            As[akg * 4 + 0][row] = v.x;
            As[akg * 4 + 1][row] = v.y;
            As[akg * 4 + 2][row] = v.z;
            As[akg * 4 + 3][row] = v.w;
        }
#pragma unroll
        for (int i2 = 0; i2 < 2; i2++)
            *(float4*)&Bs[bk + 8 * i2][bo] =
                *(const float4*)&wh[(size_t)(k0 + bk + 8 * i2) * FF + bo];
        __syncthreads();
#pragma unroll
        for (int kk = 0; kk < 16; kk++) {
            float4 a0 = *(const float4*)&As[kk][ty * 8];
            float4 a1 = *(const float4*)&As[kk][ty * 8 + 4];
            float4 b0 = *(const float4*)&Bs[kk][tx * 8];
            float4 b1 = *(const float4*)&Bs[kk][tx * 8 + 4];
            float av[8] = {a0.x, a0.y, a0.z, a0.w, a1.x, a1.y, a1.z, a1.w};
            float bv[8] = {b0.x, b0.y, b0.z, b0.w, b1.x, b1.y, b1.z, b1.w};
#pragma unroll
            for (int r = 0; r < 8; r++)
#pragma unroll
                for (int c = 0; c < 8; c++)
                    acc[r][c] = fmaf(av[r], bv[c], acc[r][c]);
        }
        __syncthreads();
    }

    float* hpo = g_hp + (size_t)((b * HH + h) * NN + n0) * FF;
    float sp[8], dp[8];
#pragma unroll
    for (int r = 0; r < 8; r++) {
        int row = ty * 8 + r;
        *(float4*)&hpo[(size_t)row * FF + tx * 8] =
            make_float4(acc[r][0], acc[r][1], acc[r][2], acc[r][3]);
        *(float4*)&hpo[(size_t)row * FF + tx * 8 + 4] =
            make_float4(acc[r][4], acc[r][5], acc[r][6], acc[r][7]);
        float s = 0.0f, d = 0.0f;
#pragma unroll
        for (int c = 0; c < 8; c++) {
            float t = tanhf(acc[r][c]);
            s = fmaf(t, sa[tx * 8 + c], s);
            d = fmaf(t, da[tx * 8 + c], d);
        }
        sp[r] = s; dp[r] = d;
    }
#pragma unroll
    for (int r = 0; r < 8; r++) red[ty * 8 + r][tx] = sp[r];
    __syncthreads();
    if (tid < 128) {
        float s = 0.0f;
#pragma unroll
        for (int c = 0; c < 16; c++) s += red[tid][c];
        g_s[(b * HH + h) * NN + n0 + tid] = s;
    }
    __syncthreads();
#pragma unroll
    for (int r = 0; r < 8; r++) red[ty * 8 + r][tx] = dp[r];
    __syncthreads();
    if (tid < 128) {
        float d = 0.0f;
#pragma unroll
        for (int c = 0; c < 16; c++) d += red[tid][c];
        g_d[(b * HH + h) * NN + n0 + tid] = d;
    }
}

// ---------------- K3a: normalized attention weights (packed {off,p}) -------
// off = (j & 255) << 9 : byte offset of j's row inside its 256-row quarter.
__global__ __launch_bounds__(256) void attn_weights() {
    const int wg   = blockIdx.x * 8 + (threadIdx.x >> 5);
    const int lane = threadIdx.x & 31;
    const int h  = wg & 7;
    const int ri = wg >> 3;
    const int b  = ri >> 10;
    const int i  = ri & 1023;

    const int cnt = g_cnt[b * NN + i];
    const int* nb = &g_nbr[(b * NN + i) * MAXN];
    const float* dd = g_d + (b * HH + h) * NN;
    const float  si = g_s[(b * HH + h) * NN + i];
    uint2* ep = &g_ep[(size_t)((b * HH + h) * NN + i) * MAXN];

    float m = -1e30f;
    float scv[8];
    int   jv[8];
#pragma unroll
    for (int t = 0; t < 8; t++) {
        int k = lane + t * 32;
        float sc = -1e30f;
        int j = 0;
        if (k < cnt) {
            j = nb[k];
            sc = si + dd[j];
            sc = sc >= 0.0f ? sc : 0.2f * sc;
        }
        jv[t] = j;
        scv[t] = sc;
        m = fmaxf(m, sc);
    }
#pragma unroll
    for (int off = 16; off > 0; off >>= 1)
        m = fmaxf(m, __shfl_xor_sync(0xffffffffu, m, off));

    float ssum = 0.0f;
    float ev[8];
#pragma unroll
    for (int t = 0; t < 8; t++) {
        int k = lane + t * 32;
        float e = 0.0f;
        if (k < cnt) e = __expf(scv[t] - m);
        ev[t] = e;
        ssum += e;
    }
#pragma unroll
    for (int off = 16; off > 0; off >>= 1)
        ssum += __shfl_xor_sync(0xffffffffu, ssum, off);
    const float wsc = (1.0f / (float)HH) / ssum;

#pragma unroll
    for (int t = 0; t < 8; t++) {
        int k = lane + t * 32;
        if (k < cnt)
            ep[k] = make_uint2((unsigned)((jv[t] & 255) << 9),
                               __float_as_uint(ev[t] * wsc));
    }
}

// ---------------- K3b: quarter-owned smem gather (single pass) -------------
// grid (4 quarters, H, B) = 256 CTAs, 1024 thr, 128 KB dyn smem.
// CTA stages its 256-row hp quarter once, processes ALL 1024 dst rows' edges
// in that quarter, writes disjoint partial slot po4[q].
__global__ __launch_bounds__(1024) void gat_gather() {
    extern __shared__ float hp_s[];       // [256][128]
    const int q   = blockIdx.x;           // 0..3
    const int h   = blockIdx.y;
    const int b   = blockIdx.z;
    const int tid = threadIdx.x;
    const int w   = tid >> 5;             // 0..31
    const int lane = tid & 31;
    const int bh  = b * HH + h;

    const float* src = g_hp + ((size_t)bh * NN + q * 256) * FF;
#pragma unroll
    for (int it = 0; it < 8; it++) {
        int idx = tid + it * 1024;        // 8192 float4 = 128 KB
        *(float4*)&hp_s[idx * 4] = *(const float4*)&src[idx * 4];
    }
    __syncthreads();

    const char* hpb = (const char*)hp_s;
    const int lane16 = lane * 16;
    float* po = g_po4 + ((size_t)q * BB * HH + bh) * NN * FF;

#pragma unroll 1
    for (int ii = 0; ii < 32; ii++) {
        const int i = ii * 32 + w;
        const int4 qq = *(const int4*)&g_qoff[(b * NN + i) * 4];
        const int lo = (q == 0) ? 0 :
                       (q == 1) ? qq.x : (q == 2) ? qq.y : qq.z;
        const int hi = (q == 0) ? qq.x :
                       (q == 1) ? qq.y : (q == 2) ? qq.z : qq.w;
        const uint2* ep = &g_ep[(size_t)(bh * NN + i) * MAXN];

        float ax = 0.0f, ay = 0.0f, az = 0.0f, aw2 = 0.0f;
        for (int k0 = lo; k0 < hi; k0 += 8) {
            uint2 r[8];
#pragma unroll
            for (int t = 0; t < 8; t++)
                r[t] = (k0 + t < hi) ? __ldg(ep + k0 + t)
                                     : make_uint2(0u, 0u);
#pragma unroll
            for (int t = 0; t < 8; t++) {
                const float p = __uint_as_float(r[t].y);
                float4 v = *(const float4*)(hpb + r[t].x + lane16);
                ax  = fmaf(p, v.x, ax);
                ay  = fmaf(p, v.y, ay);
                az  = fmaf(p, v.z, az);
                aw2 = fmaf(p, v.w, aw2);
            }
        }
        *(float4*)&po[(size_t)i * FF + lane * 4] =
            make_float4(ax, ay, az, aw2);
    }
}

// ---------------- K3c: reduce 4 quarters x 8 heads + bias (+ReLU) ----------
__global__ __launch_bounds__(256) void head_reduce(const float* __restrict__ bias,
                                                   float* __restrict__ xout,
                                                   int do_relu) {
    const int idx = blockIdx.x * 256 + threadIdx.x;
    const int ig  = idx >> 5;
    const int c4  = idx & 31;
    const int b   = ig >> 10;
    const int i   = ig & 1023;

    float ax = 0.0f, ay = 0.0f, az = 0.0f, aw = 0.0f;
#pragma unroll
    for (int qh = 0; qh < 4 * HH; qh++) {
        const int q = qh >> 3;
        const int h = qh & 7;
        const float4 v = *(const float4*)
            &g_po4[(((size_t)q * BB * HH + b * HH + h) * NN + i) * FF + c4 * 4];
        ax += v.x; ay += v.y; az += v.z; aw += v.w;
    }
    const float4 bv = *(const float4*)&bias[c4 * 4];
    ax += bv.x; ay += bv.y; az += bv.z; aw += bv.w;
    if (do_relu) {
        ax = fmaxf(ax, 0.0f); ay = fmaxf(ay, 0.0f);
        az = fmaxf(az, 0.0f); aw = fmaxf(aw, 0.0f);
    }
    *(float4*)&xout[(size_t)(b * NN + i) * FF + c4 * 4] = make_float4(ax, ay, az, aw);
}

// ---------------- K4/K5: concat max-pool + linear --------------------------
__global__ __launch_bounds__(PRED_IN) void pool1() {
    const int chunk = blockIdx.x;
    const int b     = blockIdx.y;
    const int f     = threadIdx.x;
    const float* src; int fo;
    if (f < 128)       { src = g_x1; fo = f; }
    else if (f < 256)  { src = g_x2; fo = f - 128; }
    else               { src = g_x3; fo = f - 256; }
    src += (size_t)b * NN * FF + fo;
    const int n0 = chunk * 128;
    float m = -INFINITY;
#pragma unroll 8
    for (int n = 0; n < 128; n++)
        m = fmaxf(m, src[(size_t)(n0 + n) * FF]);
    g_pmax[(b * 8 + chunk) * PRED_IN + f] = m;
}

__global__ __launch_bounds__(PRED_IN) void pool2(const float* __restrict__ pw,
                                                 const float* __restrict__ pb,
                                                 float* __restrict__ out) {
    __shared__ float pooled[PRED_IN];
    const int b = blockIdx.x;
    const int f = threadIdx.x;
    float m = -INFINITY;
#pragma unroll
    for (int c = 0; c < 8; c++)
        m = fmaxf(m, g_pmax[(b * 8 + c) * PRED_IN + f]);
    pooled[f] = m;
    __syncthreads();
    if (f < LDIM) {
        float acc = pb[f];
        for (int k = 0; k < PRED_IN; k++)
            acc = fmaf(pooled[k], pw[k * LDIM + f], acc);
        out[b * LDIM + f] = acc;
    }
}

// ---------------- launch ----------------------------------------------------
extern "C" void kernel_launch(void* const* d_in, const int* in_sizes, int n_in,
                              void* d_out, int out_size) {
    const float* x   = (const float*)d_in[0];
    const float* adj = (const float*)d_in[1];
    const float* w1  = (const float*)d_in[2];
    const float* as1 = (const float*)d_in[3];
    const float* ad1 = (const float*)d_in[4];
    const float* b1  = (const float*)d_in[5];
    const float* w2  = (const float*)d_in[6];
    const float* as2 = (const float*)d_in[7];
    const float* ad2 = (const float*)d_in[8];
    const float* b2  = (const float*)d_in[9];
    const float* w3  = (const float*)d_in[10];
    const float* as3 = (const float*)d_in[11];
    const float* ad3 = (const float*)d_in[12];
    const float* b3  = (const float*)d_in[13];
    const float* pw  = (const float*)d_in[14];
    const float* pb  = (const float*)d_in[15];
    float* out = (float*)d_out;

    float* x1; cudaGetSymbolAddress((void**)&x1, g_x1);
    float* x2; cudaGetSymbolAddress((void**)&x2, g_x2);
    float* x3; cudaGetSymbolAddress((void**)&x3, g_x3);

    const int gsm = 256 * FF * sizeof(float);     // 128 KB
    static int smem_set = 0;
    if (!smem_set) {
        cudaFuncSetAttribute(gat_gather,
                             cudaFuncAttributeMaxDynamicSharedMemorySize, gsm);
        smem_set = 1;
    }

    build_nbr<<<BB * NN / 8, 256>>>(adj);

    dim3 ggrid(64, HH);
    dim3 grgrid(4, HH, BB);
    const int wgrid = BB * NN * HH / 8;
    const int hrgrid = BB * NN * FF / 4 / 256;

    gat_gemm<<<ggrid, 256>>>(x,  w1, as1, ad1);
    attn_weights<<<wgrid, 256>>>();
    gat_gather<<<grgrid, 1024, gsm>>>();
    head_reduce<<<hrgrid, 256>>>(b1, x1, 1);

    gat_gemm<<<ggrid, 256>>>(x1, w2, as2, ad2);
    attn_weights<<<wgrid, 256>>>();
    gat_gather<<<grgrid, 1024, gsm>>>();
    head_reduce<<<hrgrid, 256>>>(b2, x2, 1);

    gat_gemm<<<ggrid, 256>>>(x2, w3, as3, ad3);
    attn_weights<<<wgrid, 256>>>();
    gat_gather<<<grgrid, 1024, gsm>>>();
    head_reduce<<<hrgrid, 256>>>(b3, x3, 0);

    pool1<<<dim3(8, BB), PRED_IN>>>();
    pool2<<<BB, PRED_IN>>>(pw, pb, out);
}

// round 11
// speedup vs baseline: 2.4305x; 1.3519x over previous
#include <cuda_runtime.h>
#include <cuda_fp16.h>
#include <math.h>

#define BB   8
#define NN   1024
#define FF   128
#define HH   8
#define MAXN 256
#define PRED_IN 384
#define LDIM 2

// ---------------- device scratch ----------------
__device__ int   g_nbr[BB * NN * MAXN];              // 8 MB
__device__ int   g_cnt[BB * NN];
__device__ int   g_qoff[BB * NN * 4];                // per-row j-quartile cumulative offsets
__device__ float g_hp[BB * HH * NN * FF];            // 32 MB
__device__ float g_s[BB * HH * NN];
__device__ float g_d[BB * HH * NN];
__device__ uint2 g_ep[(size_t)BB * HH * NN * MAXN];  // packed {local byte off, p}
__device__ float g_po2[(size_t)2 * BB * HH * NN * FF]; // 67 MB half partials
__device__ float g_x1[BB * NN * FF];
__device__ float g_x2[BB * NN * FF];
__device__ float g_x3[BB * NN * FF];
__device__ float g_pmax[BB * 8 * PRED_IN];

// ---------------- K1: adjacency -> neighbor lists + quartile offsets -------
__global__ __launch_bounds__(256) void build_nbr(const float* __restrict__ adj) {
    int wgl  = blockIdx.x * 8 + (threadIdx.x >> 5);
    int lane = threadIdx.x & 31;
    int b = wgl / NN;
    int i = wgl % NN;
    const float* row = adj + (size_t)(b * NN + i) * NN;
    int base = 0;
    int qof[4];
    for (int c = 0; c < NN; c += 32) {
        float v = row[c + lane];
        unsigned m = __ballot_sync(0xffffffffu, v > 0.0f);
        if (v > 0.0f) {
            int pos = base + __popc(m & ((1u << lane) - 1u));
            if (pos < MAXN) g_nbr[(b * NN + i) * MAXN + pos] = c + lane;
        }
        base += __popc(m);
        if (((c + 32) & 255) == 0)
            qof[((c + 32) >> 8) - 1] = min(base, MAXN);
    }
    if (lane == 0) {
        g_cnt[b * NN + i] = min(base, MAXN);
        *(int4*)&g_qoff[(b * NN + i) * 4] =
            make_int4(qof[0], qof[1], qof[2], qof[3]);
    }
}

// ---------------- K2: hp = x @ w[h] + fused tanh-dot epilogue --------------
__global__ __launch_bounds__(256) void gat_gemm(const float* __restrict__ x,
                                                const float* __restrict__ w,
                                                const float* __restrict__ asrc,
                                                const float* __restrict__ adst) {
    const int mt = blockIdx.x;           // 0..63
    const int h  = blockIdx.y;
    const int b  = mt >> 3;
    const int n0 = (mt & 7) * 128;

    __shared__ float As[16][128];        // k-major
    __shared__ float Bs[16][128];
    __shared__ float sa[FF], da[FF];
    __shared__ float red[128][17];

    const int tid = threadIdx.x;
    const int tx = tid & 15;
    const int ty = tid >> 4;

    if (tid < FF) { sa[tid] = asrc[h * FF + tid]; da[tid] = adst[h * FF + tid]; }

    const float* xb = x + (size_t)(b * NN + n0) * FF;
    const float* wh = w + (size_t)h * FF * FF;

    float acc[8][8];
#pragma unroll
    for (int r = 0; r < 8; r++)
#pragma unroll
        for (int c = 0; c < 8; c++) acc[r][c] = 0.0f;

    const int arow = tid >> 2;
    const int akg  = tid & 3;
    const int bk   = tid >> 5;
    const int bo   = (tid & 31) * 4;

    for (int k0 = 0; k0 < FF; k0 += 16) {
#pragma unroll
        for (int i2 = 0; i2 < 2; i2++) {
            int row = arow + i2 * 64;
            float4 v = *(const float4*)&xb[(size_t)row * FF + k0 + akg * 4];
            As[akg * 4 + 0][row] = v.x;
            As[akg * 4 + 1][row] = v.y;
            As[akg * 4 + 2][row] = v.z;
            As[akg * 4 + 3][row] = v.w;
        }
#pragma unroll
        for (int i2 = 0; i2 < 2; i2++)
            *(float4*)&Bs[bk + 8 * i2][bo] =
                *(const float4*)&wh[(size_t)(k0 + bk + 8 * i2) * FF + bo];
        __syncthreads();
#pragma unroll
        for (int kk = 0; kk < 16; kk++) {
            float4 a0 = *(const float4*)&As[kk][ty * 8];
            float4 a1 = *(const float4*)&As[kk][ty * 8 + 4];
            float4 b0 = *(const float4*)&Bs[kk][tx * 8];
            float4 b1 = *(const float4*)&Bs[kk][tx * 8 + 4];
            float av[8] = {a0.x, a0.y, a0.z, a0.w, a1.x, a1.y, a1.z, a1.w};
            float bv[8] = {b0.x, b0.y, b0.z, b0.w, b1.x, b1.y, b1.z, b1.w};
#pragma unroll
            for (int r = 0; r < 8; r++)
#pragma unroll
                for (int c = 0; c < 8; c++)
                    acc[r][c] = fmaf(av[r], bv[c], acc[r][c]);
        }
        __syncthreads();
    }

    float* hpo = g_hp + (size_t)((b * HH + h) * NN + n0) * FF;
    float sp[8], dp[8];
#pragma unroll
    for (int r = 0; r < 8; r++) {
        int row = ty * 8 + r;
        *(float4*)&hpo[(size_t)row * FF + tx * 8] =
            make_float4(acc[r][0], acc[r][1], acc[r][2], acc[r][3]);
        *(float4*)&hpo[(size_t)row * FF + tx * 8 + 4] =
            make_float4(acc[r][4], acc[r][5], acc[r][6], acc[r][7]);
        float s = 0.0f, d = 0.0f;
#pragma unroll
        for (int c = 0; c < 8; c++) {
            float t = tanhf(acc[r][c]);
            s = fmaf(t, sa[tx * 8 + c], s);
            d = fmaf(t, da[tx * 8 + c], d);
        }
        sp[r] = s; dp[r] = d;
    }
#pragma unroll
    for (int r = 0; r < 8; r++) red[ty * 8 + r][tx] = sp[r];
    __syncthreads();
    if (tid < 128) {
        float s = 0.0f;
#pragma unroll
        for (int c = 0; c < 16; c++) s += red[tid][c];
        g_s[(b * HH + h) * NN + n0 + tid] = s;
    }
    __syncthreads();
#pragma unroll
    for (int r = 0; r < 8; r++) red[ty * 8 + r][tx] = dp[r];
    __syncthreads();
    if (tid < 128) {
        float d = 0.0f;
#pragma unroll
        for (int c = 0; c < 16; c++) d += red[tid][c];
        g_d[(b * HH + h) * NN + n0 + tid] = d;
    }
}

// ---------------- K3a: normalized attention weights (packed {off,p}) -------
// off = (j & 511) << 8 : byte offset of j's fp16 row inside its 512-row half.
__global__ __launch_bounds__(256) void attn_weights() {
    const int wg   = blockIdx.x * 8 + (threadIdx.x >> 5);
    const int lane = threadIdx.x & 31;
    const int h  = wg & 7;
    const int ri = wg >> 3;
    const int b  = ri >> 10;
    const int i  = ri & 1023;

    const int cnt = g_cnt[b * NN + i];
    const int* nb = &g_nbr[(b * NN + i) * MAXN];
    const float* dd = g_d + (b * HH + h) * NN;
    const float  si = g_s[(b * HH + h) * NN + i];
    uint2* ep = &g_ep[(size_t)((b * HH + h) * NN + i) * MAXN];

    float m = -1e30f;
    float scv[8];
    int   jv[8];
#pragma unroll
    for (int t = 0; t < 8; t++) {
        int k = lane + t * 32;
        float sc = -1e30f;
        int j = 0;
        if (k < cnt) {
            j = nb[k];
            sc = si + dd[j];
            sc = sc >= 0.0f ? sc : 0.2f * sc;
        }
        jv[t] = j;
        scv[t] = sc;
        m = fmaxf(m, sc);
    }
#pragma unroll
    for (int off = 16; off > 0; off >>= 1)
        m = fmaxf(m, __shfl_xor_sync(0xffffffffu, m, off));

    float ssum = 0.0f;
    float ev[8];
#pragma unroll
    for (int t = 0; t < 8; t++) {
        int k = lane + t * 32;
        float e = 0.0f;
        if (k < cnt) e = __expf(scv[t] - m);
        ev[t] = e;
        ssum += e;
    }
#pragma unroll
    for (int off = 16; off > 0; off >>= 1)
        ssum += __shfl_xor_sync(0xffffffffu, ssum, off);
    const float wsc = (1.0f / (float)HH) / ssum;

#pragma unroll
    for (int t = 0; t < 8; t++) {
        int k = lane + t * 32;
        if (k < cnt)
            ep[k] = make_uint2((unsigned)((jv[t] & 511) << 8),
                               __float_as_uint(ev[t] * wsc));
    }
}

// ---------------- K3b: half-owned fp16 smem gather -------------------------
// grid (2 halves, H, B) = 128 CTAs, 1024 thr, 128 KB dyn smem (fp16 rows).
// Warp = two 16-lane groups; group owns a dst row, lane owns 8 columns.
// One LDS.128 services 2 edges (256 B fp16 row each).
__global__ __launch_bounds__(1024) void gat_gather() {
    extern __shared__ __align__(16) char hpb[];   // [512][128] fp16 = 128 KB
    const int q   = blockIdx.x;           // 0..1
    const int h   = blockIdx.y;
    const int b   = blockIdx.z;
    const int tid = threadIdx.x;
    const int w    = tid >> 5;            // 0..31
    const int lane = tid & 31;
    const int group = lane >> 4;          // 0..1
    const int gl    = lane & 15;          // 8-col chunk
    const int bh  = b * HH + h;

    // stage fp32 -> fp16 (512 rows x 128 cols)
    const float* src = g_hp + ((size_t)bh * NN + q * 512) * FF;
    __half2* hs = (__half2*)hpb;
#pragma unroll
    for (int it = 0; it < 16; it++) {
        int idx = tid + it * 1024;        // 16384 float4 groups
        float4 v = *(const float4*)&src[(size_t)idx * 4];
        hs[idx * 2 + 0] = __floats2half2_rn(v.x, v.y);
        hs[idx * 2 + 1] = __floats2half2_rn(v.z, v.w);
    }
    __syncthreads();

    float* po = g_po2 + ((size_t)q * BB * HH + bh) * NN * FF;
    const int gl16 = gl * 16;

#pragma unroll 1
    for (int ii = 0; ii < 16; ii++) {
        const int i = ii * 64 + w * 2 + group;
        const int4 qq = *(const int4*)&g_qoff[(b * NN + i) * 4];
        const int lo = q ? qq.y : 0;
        const int hi = q ? qq.w : qq.y;
        const uint2* ep = &g_ep[(size_t)(bh * NN + i) * MAXN];

        float a0 = 0.f, a1 = 0.f, a2 = 0.f, a3 = 0.f;
        float a4 = 0.f, a5 = 0.f, a6 = 0.f, a7 = 0.f;
        for (int k0 = lo; k0 < hi; k0 += 8) {
            uint2 r[8];
#pragma unroll
            for (int t = 0; t < 8; t++)
                r[t] = (k0 + t < hi) ? __ldg(ep + k0 + t)
                                     : make_uint2(0u, 0u);
#pragma unroll
            for (int t = 0; t < 8; t++) {
                const float p = __uint_as_float(r[t].y);
                uint4 hv = *(const uint4*)(hpb + r[t].x + gl16);
                float2 f0 = __half22float2(*(__half2*)&hv.x);
                float2 f1 = __half22float2(*(__half2*)&hv.y);
                float2 f2 = __half22float2(*(__half2*)&hv.z);
                float2 f3 = __half22float2(*(__half2*)&hv.w);
                a0 = fmaf(p, f0.x, a0); a1 = fmaf(p, f0.y, a1);
                a2 = fmaf(p, f1.x, a2); a3 = fmaf(p, f1.y, a3);
                a4 = fmaf(p, f2.x, a4); a5 = fmaf(p, f2.y, a5);
                a6 = fmaf(p, f3.x, a6); a7 = fmaf(p, f3.y, a7);
            }
        }
        float* dst = &po[(size_t)i * FF + gl * 8];
        *(float4*)dst       = make_float4(a0, a1, a2, a3);
        *(float4*)(dst + 4) = make_float4(a4, a5, a6, a7);
    }
}

// ---------------- K3c: reduce 2 halves x 8 heads + bias (+ReLU) ------------
__global__ __launch_bounds__(256) void head_reduce(const float* __restrict__ bias,
                                                   float* __restrict__ xout,
                                                   int do_relu) {
    const int idx = blockIdx.x * 256 + threadIdx.x;
    const int ig  = idx >> 5;
    const int c4  = idx & 31;
    const int b   = ig >> 10;
    const int i   = ig & 1023;

    float ax = 0.0f, ay = 0.0f, az = 0.0f, aw = 0.0f;
#pragma unroll
    for (int qh = 0; qh < 2 * HH; qh++) {
        const int q = qh >> 3;
        const int h = qh & 7;
        const float4 v = *(const float4*)
            &g_po2[(((size_t)q * BB * HH + b * HH + h) * NN + i) * FF + c4 * 4];
        ax += v.x; ay += v.y; az += v.z; aw += v.w;
    }
    const float4 bv = *(const float4*)&bias[c4 * 4];
    ax += bv.x; ay += bv.y; az += bv.z; aw += bv.w;
    if (do_relu) {
        ax = fmaxf(ax, 0.0f); ay = fmaxf(ay, 0.0f);
        az = fmaxf(az, 0.0f); aw = fmaxf(aw, 0.0f);
    }
    *(float4*)&xout[(size_t)(b * NN + i) * FF + c4 * 4] = make_float4(ax, ay, az, aw);
}

// ---------------- K4/K5: concat max-pool + linear --------------------------
__global__ __launch_bounds__(PRED_IN) void pool1() {
    const int chunk = blockIdx.x;
    const int b     = blockIdx.y;
    const int f     = threadIdx.x;
    const float* src; int fo;
    if (f < 128)       { src = g_x1; fo = f; }
    else if (f < 256)  { src = g_x2; fo = f - 128; }
    else               { src = g_x3; fo = f - 256; }
    src += (size_t)b * NN * FF + fo;
    const int n0 = chunk * 128;
    float m = -INFINITY;
#pragma unroll 8
    for (int n = 0; n < 128; n++)
        m = fmaxf(m, src[(size_t)(n0 + n) * FF]);
    g_pmax[(b * 8 + chunk) * PRED_IN + f] = m;
}

__global__ __launch_bounds__(PRED_IN) void pool2(const float* __restrict__ pw,
                                                 const float* __restrict__ pb,
                                                 float* __restrict__ out) {
    __shared__ float pooled[PRED_IN];
    const int b = blockIdx.x;
    const int f = threadIdx.x;
    float m = -INFINITY;
#pragma unroll
    for (int c = 0; c < 8; c++)
        m = fmaxf(m, g_pmax[(b * 8 + c) * PRED_IN + f]);
    pooled[f] = m;
    __syncthreads();
    if (f < LDIM) {
        float acc = pb[f];
        for (int k = 0; k < PRED_IN; k++)
            acc = fmaf(pooled[k], pw[k * LDIM + f], acc);
        out[b * LDIM + f] = acc;
    }
}

// ---------------- launch ----------------------------------------------------
extern "C" void kernel_launch(void* const* d_in, const int* in_sizes, int n_in,
                              void* d_out, int out_size) {
    const float* x   = (const float*)d_in[0];
    const float* adj = (const float*)d_in[1];
    const float* w1  = (const float*)d_in[2];
    const float* as1 = (const float*)d_in[3];
    const float* ad1 = (const float*)d_in[4];
    const float* b1  = (const float*)d_in[5];
    const float* w2  = (const float*)d_in[6];
    const float* as2 = (const float*)d_in[7];
    const float* ad2 = (const float*)d_in[8];
    const float* b2  = (const float*)d_in[9];
    const float* w3  = (const float*)d_in[10];
    const float* as3 = (const float*)d_in[11];
    const float* ad3 = (const float*)d_in[12];
    const float* b3  = (const float*)d_in[13];
    const float* pw  = (const float*)d_in[14];
    const float* pb  = (const float*)d_in[15];
    float* out = (float*)d_out;

    float* x1; cudaGetSymbolAddress((void**)&x1, g_x1);
    float* x2; cudaGetSymbolAddress((void**)&x2, g_x2);
    float* x3; cudaGetSymbolAddress((void**)&x3, g_x3);

    const int gsm = 512 * FF * sizeof(__half);    // 128 KB
    static int smem_set = 0;
    if (!smem_set) {
        cudaFuncSetAttribute(gat_gather,
                             cudaFuncAttributeMaxDynamicSharedMemorySize, gsm);
        smem_set = 1;
    }

    build_nbr<<<BB * NN / 8, 256>>>(adj);

    dim3 ggrid(64, HH);
    dim3 grgrid(2, HH, BB);
    const int wgrid = BB * NN * HH / 8;
    const int hrgrid = BB * NN * FF / 4 / 256;

    gat_gemm<<<ggrid, 256>>>(x,  w1, as1, ad1);
    attn_weights<<<wgrid, 256>>>();
    gat_gather<<<grgrid, 1024, gsm>>>();
    head_reduce<<<hrgrid, 256>>>(b1, x1, 1);

    gat_gemm<<<ggrid, 256>>>(x1, w2, as2, ad2);
    attn_weights<<<wgrid, 256>>>();
    gat_gather<<<grgrid, 1024, gsm>>>();
    head_reduce<<<hrgrid, 256>>>(b2, x2, 1);

    gat_gemm<<<ggrid, 256>>>(x2, w3, as3, ad3);
    attn_weights<<<wgrid, 256>>>();
    gat_gather<<<grgrid, 1024, gsm>>>();
    head_reduce<<<hrgrid, 256>>>(b3, x3, 0);

    pool1<<<dim3(8, BB), PRED_IN>>>();
    pool2<<<BB, PRED_IN>>>(pw, pb, out);
}

// round 12
// speedup vs baseline: 2.9170x; 1.2002x over previous
#include <cuda_runtime.h>
#include <cuda_fp16.h>
#include <math.h>

#define BB   8
#define NN   1024
#define FF   128
#define HH   8
#define MAXN 256
#define PRED_IN 384
#define LDIM 2
#define ASTRIDE 136   // fp16 smem row stride (272 B = 17*16, uint4-clean, bank-skewed)

// ---------------- device scratch ----------------
__device__ int    g_nbr[BB * NN * MAXN];
__device__ int    g_cnt[BB * NN];
__device__ int    g_qoff[BB * NN * 4];
__device__ __half g_hp16[(size_t)BB * HH * NN * FF];   // 16 MB fp16 hp
__device__ float  g_s[BB * HH * NN];
__device__ float  g_d[BB * HH * NN];
__device__ uint2  g_ep[(size_t)BB * HH * NN * MAXN];
__device__ float  g_po2[(size_t)2 * BB * HH * NN * FF];
__device__ float  g_x1[BB * NN * FF];
__device__ float  g_x2[BB * NN * FF];
__device__ float  g_x3[BB * NN * FF];
__device__ float  g_pmax[BB * 8 * PRED_IN];

// ---------------- K1: adjacency -> neighbor lists + quartile offsets -------
__global__ __launch_bounds__(256) void build_nbr(const float* __restrict__ adj) {
    int wgl  = blockIdx.x * 8 + (threadIdx.x >> 5);
    int lane = threadIdx.x & 31;
    int b = wgl / NN;
    int i = wgl % NN;
    const float* row = adj + (size_t)(b * NN + i) * NN;
    int base = 0;
    int qof[4];
    for (int c = 0; c < NN; c += 32) {
        float v = row[c + lane];
        unsigned m = __ballot_sync(0xffffffffu, v > 0.0f);
        if (v > 0.0f) {
            int pos = base + __popc(m & ((1u << lane) - 1u));
            if (pos < MAXN) g_nbr[(b * NN + i) * MAXN + pos] = c + lane;
        }
        base += __popc(m);
        if (((c + 32) & 255) == 0)
            qof[((c + 32) >> 8) - 1] = min(base, MAXN);
    }
    if (lane == 0) {
        g_cnt[b * NN + i] = min(base, MAXN);
        *(int4*)&g_qoff[(b * NN + i) * 4] =
            make_int4(qof[0], qof[1], qof[2], qof[3]);
    }
}

// ---------------- K2: fp16 tensor-core GEMM + fused tanh-dot epilogue ------
// grid (64 mtiles, H), 256 thr (8 warps, 4x2). CTA tile 128x128, full K=128.
#define MMA16816(d, a, b) asm volatile( \
    "mma.sync.aligned.m16n8k16.row.col.f32.f16.f16.f32 " \
    "{%0,%1,%2,%3}, {%4,%5,%6,%7}, {%8,%9}, {%0,%1,%2,%3};" \
    : "+f"(d[0]), "+f"(d[1]), "+f"(d[2]), "+f"(d[3]) \
    : "r"(a[0]), "r"(a[1]), "r"(a[2]), "r"(a[3]), "r"(b[0]), "r"(b[1]))

__global__ __launch_bounds__(256) void gat_gemm(const float* __restrict__ x,
                                                const float* __restrict__ w,
                                                const float* __restrict__ asrc,
                                                const float* __restrict__ adst) {
    extern __shared__ __align__(16) char dynsm[];
    __half* A_s  = (__half*)dynsm;                          // [128][136]
    __half* Bt_s = (__half*)(dynsm + 128 * ASTRIDE * 2);    // [128][136] (n-major)
    float*  redS = (float*)(dynsm + 2 * 128 * ASTRIDE * 2); // [128][2]
    float*  redD = redS + 256;                              // [128][2]
    float*  sa   = redD + 256;                              // [128]
    float*  da   = sa + 128;                                // [128]

    const int mt  = blockIdx.x;          // 0..63
    const int h   = blockIdx.y;
    const int b   = mt >> 3;
    const int n0m = (mt & 7) * 128;      // row block of x
    const int bh  = b * HH + h;

    const int tid  = threadIdx.x;
    const int warp = tid >> 5;
    const int lane = tid & 31;
    const int wm   = warp & 3;           // 0..3 (32 rows each)
    const int wn   = warp >> 2;          // 0..1 (64 cols each)
    const int g    = lane >> 2;          // 0..7
    const int tq   = lane & 3;           // 0..3

    if (tid < FF) { sa[tid] = asrc[h * FF + tid]; da[tid] = adst[h * FF + tid]; }

    // stage A = x tile (fp32 -> fp16)
    const float* xb = x + (size_t)(b * NN + n0m) * FF;
#pragma unroll
    for (int it = 0; it < 16; it++) {
        int idx = tid + it * 256;        // 4096 float4
        int row = idx >> 5;
        int kq  = (idx & 31) * 4;
        float4 v = *(const float4*)&xb[(size_t)row * FF + kq];
        __half2 h01 = __floats2half2_rn(v.x, v.y);
        __half2 h23 = __floats2half2_rn(v.z, v.w);
        *(__half2*)&A_s[row * ASTRIDE + kq]     = h01;
        *(__half2*)&A_s[row * ASTRIDE + kq + 2] = h23;
    }
    // stage Bt = w[h] transposed (k-major gmem -> n-major fp16 smem)
    const float* wh = w + (size_t)h * FF * FF;
#pragma unroll
    for (int it = 0; it < 16; it++) {
        int idx = tid + it * 256;
        int k  = idx >> 5;
        int nq = (idx & 31) * 4;
        float4 v = *(const float4*)&wh[(size_t)k * FF + nq];
        Bt_s[(nq + 0) * ASTRIDE + k] = __float2half_rn(v.x);
        Bt_s[(nq + 1) * ASTRIDE + k] = __float2half_rn(v.y);
        Bt_s[(nq + 2) * ASTRIDE + k] = __float2half_rn(v.z);
        Bt_s[(nq + 3) * ASTRIDE + k] = __float2half_rn(v.w);
    }
    __syncthreads();

    float acc[2][8][4];
#pragma unroll
    for (int m = 0; m < 2; m++)
#pragma unroll
        for (int n = 0; n < 8; n++)
#pragma unroll
            for (int c = 0; c < 4; c++) acc[m][n][c] = 0.0f;

    const int m0w = wm * 32;
    const int n0w = wn * 64;

#pragma unroll
    for (int ks = 0; ks < 8; ks++) {
        const int kc = ks * 16;
        unsigned a[2][4], bf[8][2];
#pragma unroll
        for (int m = 0; m < 2; m++) {
            int r0 = (m0w + m * 16 + g) * ASTRIDE + kc + tq * 2;
            a[m][0] = *(const unsigned*)&A_s[r0];
            a[m][1] = *(const unsigned*)&A_s[r0 + 8 * ASTRIDE];
            a[m][2] = *(const unsigned*)&A_s[r0 + 8];
            a[m][3] = *(const unsigned*)&A_s[r0 + 8 * ASTRIDE + 8];
        }
#pragma unroll
        for (int n = 0; n < 8; n++) {
            int rb = (n0w + n * 8 + g) * ASTRIDE + kc + tq * 2;
            bf[n][0] = *(const unsigned*)&Bt_s[rb];
            bf[n][1] = *(const unsigned*)&Bt_s[rb + 8];
        }
#pragma unroll
        for (int m = 0; m < 2; m++)
#pragma unroll
            for (int n = 0; n < 8; n++)
                MMA16816(acc[m][n], a[m], bf[n]);
    }
    __syncthreads();   // all warps done reading A_s/Bt_s; reuse A_s for hp

    // epilogue: hp -> fp16 staging + tanh dot partials (fp32 accumulators)
    float sp[2][2], dp[2][2];
#pragma unroll
    for (int m = 0; m < 2; m++)
#pragma unroll
        for (int rh = 0; rh < 2; rh++) { sp[m][rh] = 0.0f; dp[m][rh] = 0.0f; }

#pragma unroll
    for (int m = 0; m < 2; m++)
#pragma unroll
        for (int n = 0; n < 8; n++)
#pragma unroll
            for (int c = 0; c < 4; c++) {
                const int rh  = c >> 1;
                const int row = m0w + m * 16 + g + rh * 8;
                const int col = n0w + n * 8 + tq * 2 + (c & 1);
                const float v = acc[m][n][c];
                A_s[row * ASTRIDE + col] = __float2half_rn(v);
                const float t = tanhf(v);
                sp[m][rh] = fmaf(t, sa[col], sp[m][rh]);
                dp[m][rh] = fmaf(t, da[col], dp[m][rh]);
            }
    // quad-reduce (4 lanes share a row), lane tq==0 writes per-warp partial
#pragma unroll
    for (int m = 0; m < 2; m++)
#pragma unroll
        for (int rh = 0; rh < 2; rh++) {
            float s = sp[m][rh], d = dp[m][rh];
            s += __shfl_xor_sync(0xffffffffu, s, 1);
            s += __shfl_xor_sync(0xffffffffu, s, 2);
            d += __shfl_xor_sync(0xffffffffu, d, 1);
            d += __shfl_xor_sync(0xffffffffu, d, 2);
            if (tq == 0) {
                const int row = m0w + m * 16 + g + rh * 8;
                redS[row * 2 + wn] = s;
                redD[row * 2 + wn] = d;
            }
        }
    __syncthreads();

    // write hp (fp16, vectorized) and s/d
    __half* hpo = g_hp16 + ((size_t)bh * NN + n0m) * FF;
#pragma unroll
    for (int it = 0; it < 8; it++) {
        int idx = tid + it * 256;        // 2048 uint4
        int row = idx >> 4;
        int seg = (idx & 15) * 8;
        *(uint4*)&hpo[(size_t)row * FF + seg] =
            *(const uint4*)&A_s[row * ASTRIDE + seg];
    }
    if (tid < 128) {
        g_s[bh * NN + n0m + tid] = redS[tid * 2] + redS[tid * 2 + 1];
        g_d[bh * NN + n0m + tid] = redD[tid * 2] + redD[tid * 2 + 1];
    }
}

// ---------------- K3a: normalized attention weights (packed {off,p}) -------
// off = (j & 511) << 8 : byte offset of j's fp16 row inside its 512-row half.
__global__ __launch_bounds__(256) void attn_weights() {
    const int wg   = blockIdx.x * 8 + (threadIdx.x >> 5);
    const int lane = threadIdx.x & 31;
    const int h  = wg & 7;
    const int ri = wg >> 3;
    const int b  = ri >> 10;
    const int i  = ri & 1023;

    const int cnt = g_cnt[b * NN + i];
    const int* nb = &g_nbr[(b * NN + i) * MAXN];
    const float* dd = g_d + (b * HH + h) * NN;
    const float  si = g_s[(b * HH + h) * NN + i];
    uint2* ep = &g_ep[(size_t)((b * HH + h) * NN + i) * MAXN];

    float m = -1e30f;
    float scv[8];
    int   jv[8];
#pragma unroll
    for (int t = 0; t < 8; t++) {
        int k = lane + t * 32;
        float sc = -1e30f;
        int j = 0;
        if (k < cnt) {
            j = nb[k];
            sc = si + dd[j];
            sc = sc >= 0.0f ? sc : 0.2f * sc;
        }
        jv[t] = j;
        scv[t] = sc;
        m = fmaxf(m, sc);
    }
#pragma unroll
    for (int off = 16; off > 0; off >>= 1)
        m = fmaxf(m, __shfl_xor_sync(0xffffffffu, m, off));

    float ssum = 0.0f;
    float ev[8];
#pragma unroll
    for (int t = 0; t < 8; t++) {
        int k = lane + t * 32;
        float e = 0.0f;
        if (k < cnt) e = __expf(scv[t] - m);
        ev[t] = e;
        ssum += e;
    }
#pragma unroll
    for (int off = 16; off > 0; off >>= 1)
        ssum += __shfl_xor_sync(0xffffffffu, ssum, off);
    const float wsc = (1.0f / (float)HH) / ssum;

#pragma unroll
    for (int t = 0; t < 8; t++) {
        int k = lane + t * 32;
        if (k < cnt)
            ep[k] = make_uint2((unsigned)((jv[t] & 511) << 8),
                               __float_as_uint(ev[t] * wsc));
    }
}

// ---------------- K3b: half-owned fp16 smem gather -------------------------
__global__ __launch_bounds__(1024) void gat_gather() {
    extern __shared__ __align__(16) char hpb[];   // [512][128] fp16 = 128 KB
    const int q   = blockIdx.x;           // 0..1
    const int h   = blockIdx.y;
    const int b   = blockIdx.z;
    const int tid = threadIdx.x;
    const int w    = tid >> 5;
    const int lane = tid & 31;
    const int group = lane >> 4;
    const int gl    = lane & 15;
    const int bh  = b * HH + h;

    // stage (direct fp16 copy)
    const __half* src = g_hp16 + ((size_t)bh * NN + q * 512) * FF;
#pragma unroll
    for (int it = 0; it < 8; it++) {
        int idx = tid + it * 1024;        // 8192 uint4
        ((uint4*)hpb)[idx] = ((const uint4*)src)[idx];
    }
    __syncthreads();

    float* po = g_po2 + ((size_t)q * BB * HH + bh) * NN * FF;
    const int gl16 = gl * 16;

#pragma unroll 1
    for (int ii = 0; ii < 16; ii++) {
        const int i = ii * 64 + w * 2 + group;
        const int4 qq = *(const int4*)&g_qoff[(b * NN + i) * 4];
        const int lo = q ? qq.y : 0;
        const int hi = q ? qq.w : qq.y;
        const uint2* ep = &g_ep[(size_t)(bh * NN + i) * MAXN];

        float a0 = 0.f, a1 = 0.f, a2 = 0.f, a3 = 0.f;
        float a4 = 0.f, a5 = 0.f, a6 = 0.f, a7 = 0.f;
        for (int k0 = lo; k0 < hi; k0 += 8) {
            uint2 r[8];
#pragma unroll
            for (int t = 0; t < 8; t++)
                r[t] = (k0 + t < hi) ? __ldg(ep + k0 + t)
                                     : make_uint2(0u, 0u);
#pragma unroll
            for (int t = 0; t < 8; t++) {
                const float p = __uint_as_float(r[t].y);
                uint4 hv = *(const uint4*)(hpb + r[t].x + gl16);
                float2 f0 = __half22float2(*(__half2*)&hv.x);
                float2 f1 = __half22float2(*(__half2*)&hv.y);
                float2 f2 = __half22float2(*(__half2*)&hv.z);
                float2 f3 = __half22float2(*(__half2*)&hv.w);
                a0 = fmaf(p, f0.x, a0); a1 = fmaf(p, f0.y, a1);
                a2 = fmaf(p, f1.x, a2); a3 = fmaf(p, f1.y, a3);
                a4 = fmaf(p, f2.x, a4); a5 = fmaf(p, f2.y, a5);
                a6 = fmaf(p, f3.x, a6); a7 = fmaf(p, f3.y, a7);
            }
        }
        float* dst = &po[(size_t)i * FF + gl * 8];
        *(float4*)dst       = make_float4(a0, a1, a2, a3);
        *(float4*)(dst + 4) = make_float4(a4, a5, a6, a7);
    }
}

// ---------------- K3c: reduce 2 halves x 8 heads + bias (+ReLU) ------------
__global__ __launch_bounds__(256) void head_reduce(const float* __restrict__ bias,
                                                   float* __restrict__ xout,
                                                   int do_relu) {
    const int idx = blockIdx.x * 256 + threadIdx.x;
    const int ig  = idx >> 5;
    const int c4  = idx & 31;
    const int b   = ig >> 10;
    const int i   = ig & 1023;

    float ax = 0.0f, ay = 0.0f, az = 0.0f, aw = 0.0f;
#pragma unroll
    for (int qh = 0; qh < 2 * HH; qh++) {
        const int q = qh >> 3;
        const int h = qh & 7;
        const float4 v = *(const float4*)
            &g_po2[(((size_t)q * BB * HH + b * HH + h) * NN + i) * FF + c4 * 4];
        ax += v.x; ay += v.y; az += v.z; aw += v.w;
    }
    const float4 bv = *(const float4*)&bias[c4 * 4];
    ax += bv.x; ay += bv.y; az += bv.z; aw += bv.w;
    if (do_relu) {
        ax = fmaxf(ax, 0.0f); ay = fmaxf(ay, 0.0f);
        az = fmaxf(az, 0.0f); aw = fmaxf(aw, 0.0f);
    }
    *(float4*)&xout[(size_t)(b * NN + i) * FF + c4 * 4] = make_float4(ax, ay, az, aw);
}

// ---------------- K4/K5: concat max-pool + linear --------------------------
__global__ __launch_bounds__(PRED_IN) void pool1() {
    const int chunk = blockIdx.x;
    const int b     = blockIdx.y;
    const int f     = threadIdx.x;
    const float* src; int fo;
    if (f < 128)       { src = g_x1; fo = f; }
    else if (f < 256)  { src = g_x2; fo = f - 128; }
    else               { src = g_x3; fo = f - 256; }
    src += (size_t)b * NN * FF + fo;
    const int n0 = chunk * 128;
    float m = -INFINITY;
#pragma unroll 8
    for (int n = 0; n < 128; n++)
        m = fmaxf(m, src[(size_t)(n0 + n) * FF]);
    g_pmax[(b * 8 + chunk) * PRED_IN + f] = m;
}

__global__ __launch_bounds__(PRED_IN) void pool2(const float* __restrict__ pw,
                                                 const float* __restrict__ pb,
                                                 float* __restrict__ out) {
    __shared__ float pooled[PRED_IN];
    const int b = blockIdx.x;
    const int f = threadIdx.x;
    float m = -INFINITY;
#pragma unroll
    for (int c = 0; c < 8; c++)
        m = fmaxf(m, g_pmax[(b * 8 + c) * PRED_IN + f]);
    pooled[f] = m;
    __syncthreads();
    if (f < LDIM) {
        float acc = pb[f];
        for (int k = 0; k < PRED_IN; k++)
            acc = fmaf(pooled[k], pw[k * LDIM + f], acc);
        out[b * LDIM + f] = acc;
    }
}

// ---------------- launch ----------------------------------------------------
extern "C" void kernel_launch(void* const* d_in, const int* in_sizes, int n_in,
                              void* d_out, int out_size) {
    const float* x   = (const float*)d_in[0];
    const float* adj = (const float*)d_in[1];
    const float* w1  = (const float*)d_in[2];
    const float* as1 = (const float*)d_in[3];
    const float* ad1 = (const float*)d_in[4];
    const float* b1  = (const float*)d_in[5];
    const float* w2  = (const float*)d_in[6];
    const float* as2 = (const float*)d_in[7];
    const float* ad2 = (const float*)d_in[8];
    const float* b2  = (const float*)d_in[9];
    const float* w3  = (const float*)d_in[10];
    const float* as3 = (const float*)d_in[11];
    const float* ad3 = (const float*)d_in[12];
    const float* b3  = (const float*)d_in[13];
    const float* pw  = (const float*)d_in[14];
    const float* pb  = (const float*)d_in[15];
    float* out = (float*)d_out;

    float* x1; cudaGetSymbolAddress((void**)&x1, g_x1);
    float* x2; cudaGetSymbolAddress((void**)&x2, g_x2);
    float* x3; cudaGetSymbolAddress((void**)&x3, g_x3);

    const int gsm  = 512 * FF * sizeof(__half);                 // 128 KB gather
    const int gemsm = 2 * 128 * ASTRIDE * 2 + 2 * 1024 + 1024;  // 72704 B gemm
    static int smem_set = 0;
    if (!smem_set) {
        cudaFuncSetAttribute(gat_gather,
                             cudaFuncAttributeMaxDynamicSharedMemorySize, gsm);
        cudaFuncSetAttribute(gat_gemm,
                             cudaFuncAttributeMaxDynamicSharedMemorySize, gemsm);
        smem_set = 1;
    }

    build_nbr<<<BB * NN / 8, 256>>>(adj);

    dim3 ggrid(64, HH);
    dim3 grgrid(2, HH, BB);
    const int wgrid = BB * NN * HH / 8;
    const int hrgrid = BB * NN * FF / 4 / 256;

    gat_gemm<<<ggrid, 256, gemsm>>>(x,  w1, as1, ad1);
    attn_weights<<<wgrid, 256>>>();
    gat_gather<<<grgrid, 1024, gsm>>>();
    head_reduce<<<hrgrid, 256>>>(b1, x1, 1);

    gat_gemm<<<ggrid, 256, gemsm>>>(x1, w2, as2, ad2);
    attn_weights<<<wgrid, 256>>>();
    gat_gather<<<grgrid, 1024, gsm>>>();
    head_reduce<<<hrgrid, 256>>>(b2, x2, 1);

    gat_gemm<<<ggrid, 256, gemsm>>>(x2, w3, as3, ad3);
    attn_weights<<<wgrid, 256>>>();
    gat_gather<<<grgrid, 1024, gsm>>>();
    head_reduce<<<hrgrid, 256>>>(b3, x3, 0);

    pool1<<<dim3(8, BB), PRED_IN>>>();
    pool2<<<BB, PRED_IN>>>(pw, pb, out);
}